// round 7
// baseline (speedup 1.0000x reference)
#include <cuda_runtime.h>
#include <cstdint>

#define BB 16
#define NN 1024
#define FIN 64
#define HH 256

// ---------------- scratch (no allocs allowed) ----------------
__device__ float g_x[BB * NN * HH];   // 16 MB
__device__ float g_h[BB * NN * HH];   // 16 MB
__device__ float g_s1[BB * NN];
__device__ float g_s2[BB * NN];
__device__ uint32_t g_mask[BB * NN * (NN / 32)];   // 2 MB bit-packed adj
__device__ float g_pool[BB * 8 * 2 * HH];          // pooling partials

typedef unsigned long long u64;

__device__ __forceinline__ u64 pack2(float x) {
    u64 r; asm("mov.b64 %0, {%1, %1};" : "=l"(r) : "f"(x)); return r;
}
__device__ __forceinline__ void ffma2(u64& d, u64 a, u64 b) {
    asm("fma.rn.f32x2 %0, %1, %2, %0;" : "+l"(d) : "l"(a), "l"(b));
}
__device__ __forceinline__ float2 unpack2(u64 v) {
    float2 r; asm("mov.b64 {%0, %1}, %2;" : "=f"(r.x), "=f"(r.y) : "l"(v)); return r;
}
__device__ __forceinline__ float leaky(float x) { return x >= 0.f ? x : 0.2f * x; }

// ============================================================================
// pack_adj: adj float(0/1)[B*N*N] -> bitmask (1 bit per entry)
// ============================================================================
__global__ __launch_bounds__(256) void pack_adj_kernel(
    const float* __restrict__ adj, uint32_t* __restrict__ mask)
{
    const int idx = blockIdx.x * 256 + threadIdx.x;
    const float v = adj[idx];
    const unsigned bal = __ballot_sync(0xffffffffu, v > 0.f);
    if ((threadIdx.x & 31) == 0) mask[idx >> 5] = bal;
}

// ============================================================================
// embed: out[M,256] = nf[M,64] @ W[64,256] + b
// ============================================================================
__global__ __launch_bounds__(128) void embed_kernel(
    const float* __restrict__ nf, const float* __restrict__ W,
    const float* __restrict__ bias, float* __restrict__ out)
{
    __shared__ float xs[4 * FIN * 4];
    const int row0 = blockIdx.x * 16;
    const int tid = threadIdx.x;

#pragma unroll
    for (int it = 0; it < 2; it++) {
        int idx = it * 128 + tid;
        int g = idx >> 6, k = idx & 63;
        float4 v;
        v.x = nf[(size_t)(row0 + 4 * g + 0) * FIN + k];
        v.y = nf[(size_t)(row0 + 4 * g + 1) * FIN + k];
        v.z = nf[(size_t)(row0 + 4 * g + 2) * FIN + k];
        v.w = nf[(size_t)(row0 + 4 * g + 3) * FIN + k];
        *(float4*)(xs + g * (FIN * 4) + k * 4) = v;
    }
    __syncthreads();

    u64 accA[8], accB[8];
#pragma unroll
    for (int p = 0; p < 8; p++) { accA[p] = 0ULL; accB[p] = 0ULL; }

    const int c = tid;
    const float* wpA = W + c;
    const float* wpB = W + c + 128;
    float wA[4], wB[4];
#pragma unroll
    for (int u = 0; u < 4; u++) { wA[u] = wpA[u * HH]; wB[u] = wpB[u * HH]; }
    wpA += 4 * HH; wpB += 4 * HH;

    for (int kt = 0; kt < FIN; kt += 4) {
        float cAv[4], cBv[4];
#pragma unroll
        for (int u = 0; u < 4; u++) { cAv[u] = wA[u]; cBv[u] = wB[u]; }
        if (kt + 4 < FIN) {
#pragma unroll
            for (int u = 0; u < 4; u++) { wA[u] = wpA[u * HH]; wB[u] = wpB[u * HH]; }
            wpA += 4 * HH; wpB += 4 * HH;
        }
#pragma unroll
        for (int u = 0; u < 4; u++) {
            int k = kt + u;
            u64 h2a = pack2(cAv[u]);
            u64 h2b = pack2(cBv[u]);
#pragma unroll
            for (int g = 0; g < 4; g++) {
                ulonglong2 q = *(const ulonglong2*)(xs + g * (FIN * 4) + k * 4);
                ffma2(accA[2 * g], q.x, h2a); ffma2(accA[2 * g + 1], q.y, h2a);
                ffma2(accB[2 * g], q.x, h2b); ffma2(accB[2 * g + 1], q.y, h2b);
            }
        }
    }
    const float bA = bias[c], bBv = bias[c + 128];
    float* ob = out + (size_t)row0 * HH + c;
#pragma unroll
    for (int p = 0; p < 8; p++) {
        float2 vA = unpack2(accA[p]);
        float2 vB = unpack2(accB[p]);
        ob[(size_t)(2 * p) * HH]           = vA.x + bA;
        ob[(size_t)(2 * p + 1) * HH]       = vA.y + bA;
        ob[(size_t)(2 * p) * HH + 128]     = vB.x + bBv;
        ob[(size_t)(2 * p + 1) * HH + 128] = vB.y + bBv;
    }
}

// ============================================================================
// gemm256 + fused s1/s2
// ============================================================================
__global__ __launch_bounds__(128) void gemm_s1s2_kernel(
    const float* __restrict__ X, const float* __restrict__ W,
    const float* __restrict__ a1, const float* __restrict__ a2,
    float* __restrict__ hout, float* __restrict__ s1o, float* __restrict__ s2o)
{
    __shared__ float xs[4 * HH * 4];
    __shared__ float red[128];
    const int row0 = blockIdx.x * 16;
    const int tid = threadIdx.x;
    const int lane = tid & 31, wid = tid >> 5;

#pragma unroll
    for (int it = 0; it < 8; it++) {
        int idx = it * 128 + tid;
        int g = idx >> 8, k = idx & 255;
        float4 v;
        v.x = X[(size_t)(row0 + 4 * g + 0) * HH + k];
        v.y = X[(size_t)(row0 + 4 * g + 1) * HH + k];
        v.z = X[(size_t)(row0 + 4 * g + 2) * HH + k];
        v.w = X[(size_t)(row0 + 4 * g + 3) * HH + k];
        *(float4*)(xs + g * (HH * 4) + k * 4) = v;
    }
    __syncthreads();

    u64 accA[8], accB[8];
#pragma unroll
    for (int p = 0; p < 8; p++) { accA[p] = 0ULL; accB[p] = 0ULL; }

    const int c = tid;
    const float* wpA = W + c;
    const float* wpB = W + c + 128;
    float wA[4], wB[4];
#pragma unroll
    for (int u = 0; u < 4; u++) { wA[u] = wpA[u * HH]; wB[u] = wpB[u * HH]; }
    wpA += 4 * HH; wpB += 4 * HH;

    const float* xp = xs;
    for (int kt = 0; kt < HH; kt += 4) {
        float cAv[4], cBv[4];
#pragma unroll
        for (int u = 0; u < 4; u++) { cAv[u] = wA[u]; cBv[u] = wB[u]; }
        if (kt + 4 < HH) {
#pragma unroll
            for (int u = 0; u < 4; u++) { wA[u] = wpA[u * HH]; wB[u] = wpB[u * HH]; }
            wpA += 4 * HH; wpB += 4 * HH;
        }
#pragma unroll
        for (int u = 0; u < 4; u++) {
            u64 h2a = pack2(cAv[u]);
            u64 h2b = pack2(cBv[u]);
#pragma unroll
            for (int g = 0; g < 4; g++) {
                ulonglong2 q = *(const ulonglong2*)(xp + g * (HH * 4) + u * 4);
                ffma2(accA[2 * g], q.x, h2a); ffma2(accA[2 * g + 1], q.y, h2a);
                ffma2(accB[2 * g], q.x, h2b); ffma2(accB[2 * g + 1], q.y, h2b);
            }
        }
        xp += 16;
    }

    const float a1A = a1[c], a1B = a1[c + 128];
    const float a2A = a2[c], a2B = a2[c + 128];
    float s1p[16], s2p[16];
    float* ob = hout + (size_t)row0 * HH + c;
#pragma unroll
    for (int p = 0; p < 8; p++) {
        float2 vA = unpack2(accA[p]);
        float2 vB = unpack2(accB[p]);
        ob[(size_t)(2 * p) * HH]           = vA.x;
        ob[(size_t)(2 * p + 1) * HH]       = vA.y;
        ob[(size_t)(2 * p) * HH + 128]     = vB.x;
        ob[(size_t)(2 * p + 1) * HH + 128] = vB.y;
        s1p[2 * p]     = vA.x * a1A + vB.x * a1B;
        s1p[2 * p + 1] = vA.y * a1A + vB.y * a1B;
        s2p[2 * p]     = vA.x * a2A + vB.x * a2B;
        s2p[2 * p + 1] = vA.y * a2A + vB.y * a2B;
    }
#pragma unroll
    for (int r = 0; r < 16; r++) {
#pragma unroll
        for (int o = 16; o; o >>= 1) {
            s1p[r] += __shfl_xor_sync(0xffffffffu, s1p[r], o);
            s2p[r] += __shfl_xor_sync(0xffffffffu, s2p[r], o);
        }
        if (lane == 0) { red[r * 4 + wid] = s1p[r]; red[64 + r * 4 + wid] = s2p[r]; }
    }
    __syncthreads();
    if (tid < 32) {
        int r = tid & 15;
        int base = (tid < 16) ? 0 : 64;
        float s = red[base + r * 4] + red[base + r * 4 + 1] + red[base + r * 4 + 2] + red[base + r * 4 + 3];
        if (tid < 16) s1o[row0 + r] = s; else s2o[row0 + r] = s;
    }
}

// ============================================================================
// attention: out = relu( softmax_row( mask( leaky(s1_i + s2_j) ) ) @ h )
// 16 rows/block, 256 threads (1 column per thread). mask bit-packed, L2-resident.
// att smem [g][j][q] row-quads (64 KB). 3 blocks/SM -> 24 warps/SM.
// ============================================================================
__global__ __launch_bounds__(256, 3) void att_kernel(
    const uint32_t* __restrict__ mask, const float* __restrict__ h,
    const float* __restrict__ s1, const float* __restrict__ s2,
    float* __restrict__ out)
{
    extern __shared__ float att[];        // 16384 floats (64KB)
    __shared__ uint32_t msk[16 * 32];     // 2KB: 16 rows x 32 words
    __shared__ float red[128];            // 16 rows x 8 warps
    __shared__ float rinv[16];
    __shared__ float s2mx[8];
    __shared__ float s2max_sh;

    const int b = blockIdx.y;
    const int i0 = blockIdx.x * 16;
    const int tid = threadIdx.x;
    const int lane = tid & 31, wid = tid >> 5;

    // load this block's 16 mask rows (512 words, 256 threads -> uint2 each)
    {
        const uint2* mg = (const uint2*)(mask + ((size_t)b * NN + i0) * 32);
        ((uint2*)msk)[tid] = mg[tid];
    }

    const float* s2b = s2 + b * NN;
    float s2v[4];
    float m = -3.4e38f;
#pragma unroll
    for (int u = 0; u < 4; u++) { s2v[u] = s2b[u * 256 + tid]; m = fmaxf(m, s2v[u]); }
#pragma unroll
    for (int o = 16; o; o >>= 1) m = fmaxf(m, __shfl_xor_sync(0xffffffffu, m, o));
    if (lane == 0) s2mx[wid] = m;
    __syncthreads();
    if (tid == 0) {
        float mm = s2mx[0];
#pragma unroll
        for (int w = 1; w < 8; w++) mm = fmaxf(mm, s2mx[w]);
        s2max_sh = mm;
    }
    __syncthreads();
    const float s2max = s2max_sh;

    // -------- phase A: unnormalized probs into att, rowsum partials --------
#pragma unroll
    for (int g = 0; g < 4; g++) {
        float s1v[4], mi[4], sum[4];
#pragma unroll
        for (int q = 0; q < 4; q++) {
            s1v[q] = s1[b * NN + i0 + 4 * g + q];
            mi[q] = leaky(s1v[q] + s2max);
            sum[q] = 0.f;
        }
#pragma unroll
        for (int u = 0; u < 4; u++) {
            int j = u * 256 + tid;
            float s2j = s2v[u];
            float4 pv;
#pragma unroll
            for (int q = 0; q < 4; q++) {
                uint32_t mw = msk[(4 * g + q) * 32 + u * 8 + wid];  // broadcast LDS
                float e = leaky(s1v[q] + s2j);
                float p = ((mw >> lane) & 1u) ? __expf(e - mi[q]) : 0.f;
                ((float*)&pv)[q] = p;
                sum[q] += p;
            }
            *(float4*)(att + g * 4096 + j * 4) = pv;   // conflict-free STS.128
        }
        // reduce the 4 row sums of this g across the block
#pragma unroll
        for (int q = 0; q < 4; q++) {
#pragma unroll
            for (int o = 16; o; o >>= 1) sum[q] += __shfl_xor_sync(0xffffffffu, sum[q], o);
            if (lane == 0) red[(4 * g + q) * 8 + wid] = sum[q];
        }
    }
    __syncthreads();
    if (tid < 16) {
        float s = 0.f;
#pragma unroll
        for (int w = 0; w < 8; w++) s += red[tid * 8 + w];
        rinv[tid] = 1.0f / s;
    }
    __syncthreads();

    // -------- phase B: C[16,256] = att[16,1024] @ h[1024,256] --------
    u64 acc[8];
#pragma unroll
    for (int p = 0; p < 8; p++) acc[p] = 0ULL;

    const float* hp = h + (size_t)b * NN * HH + tid;    // column c = tid
    float hv[8];
#pragma unroll
    for (int u = 0; u < 8; u++) hv[u] = hp[(size_t)u * HH];

    for (int jt = 0; jt < NN; jt += 8) {
        const bool pf = (jt + 8) < NN;
#pragma unroll
        for (int u = 0; u < 8; u++) {
            const int j = jt + u;
            u64 h2 = pack2(hv[u]);
            if (pf) hv[u] = hp[(size_t)(jt + 8 + u) * HH];
#pragma unroll
            for (int g = 0; g < 4; g++) {
                ulonglong2 q = *(const ulonglong2*)(att + g * 4096 + j * 4);  // broadcast
                ffma2(acc[2 * g], q.x, h2);
                ffma2(acc[2 * g + 1], q.y, h2);
            }
        }
    }

    float* ob = out + ((size_t)b * NN + i0) * HH + tid;
#pragma unroll
    for (int p = 0; p < 8; p++) {
        float2 v = unpack2(acc[p]);
        ob[(size_t)(2 * p) * HH]     = fmaxf(v.x * rinv[2 * p], 0.f);
        ob[(size_t)(2 * p + 1) * HH] = fmaxf(v.y * rinv[2 * p + 1], 0.f);
    }
}

// ---------------- pooling partials: 8 segments of 128 rows ----------------
__global__ __launch_bounds__(256) void pool_partial_kernel(
    const float* __restrict__ x, float* __restrict__ pool)
{
    const int seg = blockIdx.x, b = blockIdx.y, c = threadIdx.x;
    const float* xb = x + ((size_t)b * NN + seg * 128) * HH + c;
    float s = 0.f, m = -3.4e38f;
#pragma unroll 8
    for (int n = 0; n < 128; n++) {
        float v = xb[(size_t)n * HH];
        s += v;
        m = fmaxf(m, v);
    }
    float* pb = pool + ((size_t)b * 8 + seg) * 2 * HH;
    pb[c] = s;
    pb[HH + c] = m;
}

// ---------------- combine + 2-layer MLP ----------------
__global__ __launch_bounds__(256) void mlp_kernel(
    const float* __restrict__ pool, const float* __restrict__ W1,
    const float* __restrict__ b1, const float* __restrict__ W2,
    const float* __restrict__ b2, float* __restrict__ gout)
{
    __shared__ float g0[HH];
    __shared__ float t1[HH];
    const int b = blockIdx.x, c = threadIdx.x;
    const float* pb = pool + (size_t)b * 8 * 2 * HH;

    float s = 0.f, m = -3.4e38f;
#pragma unroll
    for (int seg = 0; seg < 8; seg++) {
        s += pb[seg * 2 * HH + c];
        m = fmaxf(m, pb[seg * 2 * HH + HH + c]);
    }
    g0[c] = s * (1.0f / NN) + m;
    __syncthreads();

    float a = b1[c];
#pragma unroll 4
    for (int k = 0; k < HH; k++) a += g0[k] * W1[k * HH + c];
    t1[c] = fmaxf(a, 0.f);
    __syncthreads();

    float a2 = b2[c];
#pragma unroll 4
    for (int k = 0; k < HH; k++) a2 += t1[k] * W2[k * HH + c];
    gout[b * HH + c] = a2;
}

// ---------------- launch ----------------
extern "C" void kernel_launch(void* const* d_in, const int* in_sizes, int n_in,
                              void* d_out, int out_size)
{
    const float* nf   = (const float*)d_in[0];
    const float* adj  = (const float*)d_in[1];
    const float* embW = (const float*)d_in[2];
    const float* embB = (const float*)d_in[3];
    const float* W0   = (const float*)d_in[4];
    const float* a10  = (const float*)d_in[5];
    const float* a20  = (const float*)d_in[6];
    const float* W1   = (const float*)d_in[7];
    const float* a11  = (const float*)d_in[8];
    const float* a21  = (const float*)d_in[9];
    const float* gW1  = (const float*)d_in[10];
    const float* gb1  = (const float*)d_in[11];
    const float* gW2  = (const float*)d_in[12];
    const float* gb2  = (const float*)d_in[13];

    float* out  = (float*)d_out;
    float* xout = out;                              // [B,N,H]
    float* gout = out + (size_t)BB * NN * HH;       // [B,H]

    float *xb, *hb, *s1b, *s2b, *poolb;
    uint32_t* maskb;
    cudaGetSymbolAddress((void**)&xb,    g_x);
    cudaGetSymbolAddress((void**)&hb,    g_h);
    cudaGetSymbolAddress((void**)&s1b,   g_s1);
    cudaGetSymbolAddress((void**)&s2b,   g_s2);
    cudaGetSymbolAddress((void**)&maskb, g_mask);
    cudaGetSymbolAddress((void**)&poolb, g_pool);

    cudaFuncSetAttribute(att_kernel, cudaFuncAttributeMaxDynamicSharedMemorySize, 64 * 1024);

    const int mrows = BB * NN;
    dim3 blk128(128);

    pack_adj_kernel<<<BB * NN * NN / 256, 256>>>(adj, maskb);
    embed_kernel<<<mrows / 16, blk128>>>(nf, embW, embB, xb);

    // layer 0
    gemm_s1s2_kernel<<<mrows / 16, blk128>>>(xb, W0, a10, a20, hb, s1b, s2b);
    att_kernel<<<dim3(NN / 16, BB), 256, 64 * 1024>>>(maskb, hb, s1b, s2b, xb);

    // layer 1
    gemm_s1s2_kernel<<<mrows / 16, blk128>>>(xb, W1, a11, a21, hb, s1b, s2b);
    att_kernel<<<dim3(NN / 16, BB), 256, 64 * 1024>>>(maskb, hb, s1b, s2b, xout);

    // pooling + MLP head
    pool_partial_kernel<<<dim3(8, BB), 256>>>(xout, poolb);
    mlp_kernel<<<BB, 256>>>(poolb, gW1, gb1, gW2, gb2, gout);
}

// round 8
// speedup vs baseline: 1.1006x; 1.1006x over previous
#include <cuda_runtime.h>
#include <cstdint>

#define BB 16
#define NN 1024
#define FIN 64
#define HH 256

// ---------------- scratch (no allocs allowed) ----------------
__device__ float g_x[BB * NN * HH];   // 16 MB
__device__ float g_h[BB * NN * HH];   // 16 MB
__device__ float g_s1[BB * NN];
__device__ float g_s2[BB * NN];
__device__ uint32_t g_mask[BB * NN * (NN / 32)];   // 2 MB bit-packed adj
__device__ float g_pool[BB * 8 * 2 * HH];          // pooling partials

typedef unsigned long long u64;

__device__ __forceinline__ u64 pack2(float x) {
    u64 r; asm("mov.b64 %0, {%1, %1};" : "=l"(r) : "f"(x)); return r;
}
__device__ __forceinline__ void ffma2(u64& d, u64 a, u64 b) {
    asm("fma.rn.f32x2 %0, %1, %2, %0;" : "+l"(d) : "l"(a), "l"(b));
}
__device__ __forceinline__ float2 unpack2(u64 v) {
    float2 r; asm("mov.b64 {%0, %1}, %2;" : "=f"(r.x), "=f"(r.y) : "l"(v)); return r;
}
__device__ __forceinline__ float leaky(float x) { return x >= 0.f ? x : 0.2f * x; }

// ============================================================================
// pack_adj: adj float(0/1)[B*N*N] -> bitmask (1 bit per entry)
// ============================================================================
__global__ __launch_bounds__(256) void pack_adj_kernel(
    const float* __restrict__ adj, uint32_t* __restrict__ mask)
{
    const int idx = blockIdx.x * 256 + threadIdx.x;
    const float v = adj[idx];
    const unsigned bal = __ballot_sync(0xffffffffu, v > 0.f);
    if ((threadIdx.x & 31) == 0) mask[idx >> 5] = bal;
}

// ============================================================================
// embed: out[M,256] = nf[M,64] @ W[64,256] + b   (round-5 version)
// ============================================================================
__global__ __launch_bounds__(128) void embed_kernel(
    const float* __restrict__ nf, const float* __restrict__ W,
    const float* __restrict__ bias, float* __restrict__ out)
{
    __shared__ float xs[4 * FIN * 4];
    const int row0 = blockIdx.x * 16;
    const int tid = threadIdx.x;

#pragma unroll
    for (int it = 0; it < 2; it++) {
        int idx = it * 128 + tid;
        int g = idx >> 6, k = idx & 63;
        float4 v;
        v.x = nf[(size_t)(row0 + 4 * g + 0) * FIN + k];
        v.y = nf[(size_t)(row0 + 4 * g + 1) * FIN + k];
        v.z = nf[(size_t)(row0 + 4 * g + 2) * FIN + k];
        v.w = nf[(size_t)(row0 + 4 * g + 3) * FIN + k];
        *(float4*)(xs + g * (FIN * 4) + k * 4) = v;
    }
    __syncthreads();

    u64 accA[8], accB[8];
#pragma unroll
    for (int p = 0; p < 8; p++) { accA[p] = 0ULL; accB[p] = 0ULL; }

    const int c = tid;
    float wA[4], wB[4];
#pragma unroll
    for (int u = 0; u < 4; u++) { wA[u] = W[u * HH + c]; wB[u] = W[u * HH + c + 128]; }

    for (int kt = 0; kt < FIN; kt += 4) {
        float cAv[4], cBv[4];
#pragma unroll
        for (int u = 0; u < 4; u++) { cAv[u] = wA[u]; cBv[u] = wB[u]; }
        if (kt + 4 < FIN) {
#pragma unroll
            for (int u = 0; u < 4; u++) {
                wA[u] = W[(kt + 4 + u) * HH + c];
                wB[u] = W[(kt + 4 + u) * HH + c + 128];
            }
        }
#pragma unroll
        for (int u = 0; u < 4; u++) {
            int k = kt + u;
            u64 h2a = pack2(cAv[u]);
            u64 h2b = pack2(cBv[u]);
#pragma unroll
            for (int g = 0; g < 4; g++) {
                ulonglong2 q = *(const ulonglong2*)(xs + g * (FIN * 4) + k * 4);
                ffma2(accA[2 * g], q.x, h2a); ffma2(accA[2 * g + 1], q.y, h2a);
                ffma2(accB[2 * g], q.x, h2b); ffma2(accB[2 * g + 1], q.y, h2b);
            }
        }
    }
    const float bA = bias[c], bBv = bias[c + 128];
    float* ob = out + (size_t)row0 * HH + c;
#pragma unroll
    for (int p = 0; p < 8; p++) {
        float2 vA = unpack2(accA[p]);
        float2 vB = unpack2(accB[p]);
        ob[(size_t)(2 * p) * HH]           = vA.x + bA;
        ob[(size_t)(2 * p + 1) * HH]       = vA.y + bA;
        ob[(size_t)(2 * p) * HH + 128]     = vB.x + bBv;
        ob[(size_t)(2 * p + 1) * HH + 128] = vB.y + bBv;
    }
}

// ============================================================================
// gemm256 + fused s1/s2   (round-5 version)
// ============================================================================
__global__ __launch_bounds__(128) void gemm_s1s2_kernel(
    const float* __restrict__ X, const float* __restrict__ W,
    const float* __restrict__ a1, const float* __restrict__ a2,
    float* __restrict__ hout, float* __restrict__ s1o, float* __restrict__ s2o)
{
    __shared__ float xs[4 * HH * 4];
    __shared__ float red[128];
    const int row0 = blockIdx.x * 16;
    const int tid = threadIdx.x;
    const int lane = tid & 31, wid = tid >> 5;

#pragma unroll
    for (int it = 0; it < 8; it++) {
        int idx = it * 128 + tid;
        int g = idx >> 8, k = idx & 255;
        float4 v;
        v.x = X[(size_t)(row0 + 4 * g + 0) * HH + k];
        v.y = X[(size_t)(row0 + 4 * g + 1) * HH + k];
        v.z = X[(size_t)(row0 + 4 * g + 2) * HH + k];
        v.w = X[(size_t)(row0 + 4 * g + 3) * HH + k];
        *(float4*)(xs + g * (HH * 4) + k * 4) = v;
    }
    __syncthreads();

    u64 accA[8], accB[8];
#pragma unroll
    for (int p = 0; p < 8; p++) { accA[p] = 0ULL; accB[p] = 0ULL; }

    const int c = tid;
    float wA[4], wB[4];
#pragma unroll
    for (int u = 0; u < 4; u++) { wA[u] = W[u * HH + c]; wB[u] = W[u * HH + c + 128]; }

    for (int kt = 0; kt < HH; kt += 4) {
        float cAv[4], cBv[4];
#pragma unroll
        for (int u = 0; u < 4; u++) { cAv[u] = wA[u]; cBv[u] = wB[u]; }
        if (kt + 4 < HH) {
#pragma unroll
            for (int u = 0; u < 4; u++) {
                wA[u] = W[(kt + 4 + u) * HH + c];
                wB[u] = W[(kt + 4 + u) * HH + c + 128];
            }
        }
#pragma unroll
        for (int u = 0; u < 4; u++) {
            int k = kt + u;
            u64 h2a = pack2(cAv[u]);
            u64 h2b = pack2(cBv[u]);
#pragma unroll
            for (int g = 0; g < 4; g++) {
                ulonglong2 q = *(const ulonglong2*)(xs + g * (HH * 4) + k * 4);
                ffma2(accA[2 * g], q.x, h2a); ffma2(accA[2 * g + 1], q.y, h2a);
                ffma2(accB[2 * g], q.x, h2b); ffma2(accB[2 * g + 1], q.y, h2b);
            }
        }
    }

    const float a1A = a1[c], a1B = a1[c + 128];
    const float a2A = a2[c], a2B = a2[c + 128];
    float s1p[16], s2p[16];
    float* ob = hout + (size_t)row0 * HH + c;
#pragma unroll
    for (int p = 0; p < 8; p++) {
        float2 vA = unpack2(accA[p]);
        float2 vB = unpack2(accB[p]);
        ob[(size_t)(2 * p) * HH]           = vA.x;
        ob[(size_t)(2 * p + 1) * HH]       = vA.y;
        ob[(size_t)(2 * p) * HH + 128]     = vB.x;
        ob[(size_t)(2 * p + 1) * HH + 128] = vB.y;
        s1p[2 * p]     = vA.x * a1A + vB.x * a1B;
        s1p[2 * p + 1] = vA.y * a1A + vB.y * a1B;
        s2p[2 * p]     = vA.x * a2A + vB.x * a2B;
        s2p[2 * p + 1] = vA.y * a2A + vB.y * a2B;
    }
#pragma unroll
    for (int r = 0; r < 16; r++) {
#pragma unroll
        for (int o = 16; o; o >>= 1) {
            s1p[r] += __shfl_xor_sync(0xffffffffu, s1p[r], o);
            s2p[r] += __shfl_xor_sync(0xffffffffu, s2p[r], o);
        }
        if (lane == 0) { red[r * 4 + wid] = s1p[r]; red[64 + r * 4 + wid] = s2p[r]; }
    }
    __syncthreads();
    if (tid < 32) {
        int r = tid & 15;
        int base = (tid < 16) ? 0 : 64;
        float s = red[base + r * 4] + red[base + r * 4 + 1] + red[base + r * 4 + 2] + red[base + r * 4 + 3];
        if (tid < 16) s1o[row0 + r] = s; else s2o[row0 + r] = s;
    }
}

// ============================================================================
// attention: out = relu( softmax_row( mask( leaky(s1_i + s2_j) ) ) @ h )
// 16 rows/block, 128 threads. Phase B tiling: warp = (8-row group) x (128-col
// half); lane owns 4 consecutive cols. Per warp-j: 2 broadcast LDS.128 +
// 1 LDG.128 + 16 FFMA2. att smem [g][j][quad] row-quads (64 KB), 3 blocks/SM.
// ============================================================================
__global__ __launch_bounds__(128, 3) void att_kernel(
    const uint32_t* __restrict__ mask, const float* __restrict__ h,
    const float* __restrict__ s1, const float* __restrict__ s2,
    float* __restrict__ out)
{
    extern __shared__ float att[];        // 16384 floats (64KB)
    __shared__ uint32_t msk[16 * 32];     // 2KB: 16 rows x 32 words
    __shared__ float red[64];
    __shared__ float rinv[16];
    __shared__ float s2max_sh;

    const int b = blockIdx.y;
    const int i0 = blockIdx.x * 16;
    const int tid = threadIdx.x;
    const int lane = tid & 31, wid = tid >> 5;

    // load this block's 16 mask rows (512 words)
    {
        const uint4* mg = (const uint4*)(mask + ((size_t)b * NN + i0) * 32);
        ((uint4*)msk)[tid] = mg[tid];
    }

    const float* s2b = s2 + b * NN;
    float s2v[8];
    float m = -3.4e38f;
#pragma unroll
    for (int u = 0; u < 8; u++) { s2v[u] = s2b[u * 128 + tid]; m = fmaxf(m, s2v[u]); }
#pragma unroll
    for (int o = 16; o; o >>= 1) m = fmaxf(m, __shfl_xor_sync(0xffffffffu, m, o));
    if (lane == 0) red[wid] = m;
    __syncthreads();
    if (tid == 0) s2max_sh = fmaxf(fmaxf(red[0], red[1]), fmaxf(red[2], red[3]));
    __syncthreads();
    const float s2max = s2max_sh;

    // -------- phase A: unnormalized probs into att, rowsum partials --------
#pragma unroll
    for (int g = 0; g < 4; g++) {
        float s1v[4], mi[4], sum[4];
#pragma unroll
        for (int q = 0; q < 4; q++) {
            s1v[q] = s1[b * NN + i0 + 4 * g + q];
            mi[q] = leaky(s1v[q] + s2max);
            sum[q] = 0.f;
        }
#pragma unroll 2
        for (int u = 0; u < 8; u++) {
            int j = u * 128 + tid;
            float s2j = s2v[u];
            float4 pv;
#pragma unroll
            for (int q = 0; q < 4; q++) {
                uint32_t mw = msk[(4 * g + q) * 32 + u * 4 + wid];  // broadcast LDS
                float e = leaky(s1v[q] + s2j);
                float p = ((mw >> lane) & 1u) ? __expf(e - mi[q]) : 0.f;
                ((float*)&pv)[q] = p;
                sum[q] += p;
            }
            *(float4*)(att + g * 4096 + j * 4) = pv;   // conflict-free STS.128
        }
#pragma unroll
        for (int q = 0; q < 4; q++) {
#pragma unroll
            for (int o = 16; o; o >>= 1) sum[q] += __shfl_xor_sync(0xffffffffu, sum[q], o);
            if (lane == 0) red[(4 * g + q) * 4 + wid] = sum[q];
        }
    }
    __syncthreads();
    if (tid < 16) {
        float s = red[tid * 4] + red[tid * 4 + 1] + red[tid * 4 + 2] + red[tid * 4 + 3];
        rinv[tid] = 1.0f / s;
    }
    __syncthreads();

    // -------- phase B: C[16,256] = att[16,1024] @ h[1024,256] --------
    // warp: rows rg*8..rg*8+7 (quads 2rg, 2rg+1), cols half*128 + lane*4 .. +3
    const int rg = wid >> 1;
    const int half = wid & 1;

    u64 acc[4][4];   // [row-pair][col]  row-pair rp covers rows rg*8+2rp, +1
#pragma unroll
    for (int rp = 0; rp < 4; rp++)
#pragma unroll
        for (int cc = 0; cc < 4; cc++) acc[rp][cc] = 0ULL;

    const float* hp = h + (size_t)b * NN * HH + half * 128 + lane * 4;
    const float* aq0p = att + (2 * rg) * 4096;
    const float* aq1p = aq0p + 4096;

    float4 hbuf[4];
#pragma unroll
    for (int u = 0; u < 4; u++) hbuf[u] = *(const float4*)(hp + (size_t)u * HH);

    for (int jt = 0; jt < NN; jt += 4) {
        const bool pf = (jt + 4) < NN;
#pragma unroll
        for (int u = 0; u < 4; u++) {
            const int j = jt + u;
            float4 hv = hbuf[u];
            if (pf) hbuf[u] = *(const float4*)(hp + (size_t)(jt + 4 + u) * HH);
            ulonglong2 aq0 = *(const ulonglong2*)(aq0p + j * 4);  // rows (0,1),(2,3) of quad 2rg
            ulonglong2 aq1 = *(const ulonglong2*)(aq1p + j * 4);  // rows of quad 2rg+1
            u64 h0 = pack2(hv.x), h1 = pack2(hv.y), h2 = pack2(hv.z), h3 = pack2(hv.w);
            ffma2(acc[0][0], aq0.x, h0); ffma2(acc[0][1], aq0.x, h1);
            ffma2(acc[0][2], aq0.x, h2); ffma2(acc[0][3], aq0.x, h3);
            ffma2(acc[1][0], aq0.y, h0); ffma2(acc[1][1], aq0.y, h1);
            ffma2(acc[1][2], aq0.y, h2); ffma2(acc[1][3], aq0.y, h3);
            ffma2(acc[2][0], aq1.x, h0); ffma2(acc[2][1], aq1.x, h1);
            ffma2(acc[2][2], aq1.x, h2); ffma2(acc[2][3], aq1.x, h3);
            ffma2(acc[3][0], aq1.y, h0); ffma2(acc[3][1], aq1.y, h1);
            ffma2(acc[3][2], aq1.y, h2); ffma2(acc[3][3], aq1.y, h3);
        }
    }

    // epilogue: rows rg*8+2rp (+1), cols half*128+lane*4
    float* ob = out + ((size_t)b * NN + i0 + rg * 8) * HH + half * 128 + lane * 4;
#pragma unroll
    for (int rp = 0; rp < 4; rp++) {
        const float ri0 = rinv[rg * 8 + 2 * rp];
        const float ri1 = rinv[rg * 8 + 2 * rp + 1];
        float4 r0v, r1v;
        float2 v;
        v = unpack2(acc[rp][0]); r0v.x = fmaxf(v.x * ri0, 0.f); r1v.x = fmaxf(v.y * ri1, 0.f);
        v = unpack2(acc[rp][1]); r0v.y = fmaxf(v.x * ri0, 0.f); r1v.y = fmaxf(v.y * ri1, 0.f);
        v = unpack2(acc[rp][2]); r0v.z = fmaxf(v.x * ri0, 0.f); r1v.z = fmaxf(v.y * ri1, 0.f);
        v = unpack2(acc[rp][3]); r0v.w = fmaxf(v.x * ri0, 0.f); r1v.w = fmaxf(v.y * ri1, 0.f);
        *(float4*)(ob + (size_t)(2 * rp) * HH)     = r0v;
        *(float4*)(ob + (size_t)(2 * rp + 1) * HH) = r1v;
    }
}

// ---------------- pooling partials: 8 segments of 128 rows ----------------
__global__ __launch_bounds__(256) void pool_partial_kernel(
    const float* __restrict__ x, float* __restrict__ pool)
{
    const int seg = blockIdx.x, b = blockIdx.y, c = threadIdx.x;
    const float* xb = x + ((size_t)b * NN + seg * 128) * HH + c;
    float s = 0.f, m = -3.4e38f;
#pragma unroll 8
    for (int n = 0; n < 128; n++) {
        float v = xb[(size_t)n * HH];
        s += v;
        m = fmaxf(m, v);
    }
    float* pb = pool + ((size_t)b * 8 + seg) * 2 * HH;
    pb[c] = s;
    pb[HH + c] = m;
}

// ---------------- combine + 2-layer MLP ----------------
__global__ __launch_bounds__(256) void mlp_kernel(
    const float* __restrict__ pool, const float* __restrict__ W1,
    const float* __restrict__ b1, const float* __restrict__ W2,
    const float* __restrict__ b2, float* __restrict__ gout)
{
    __shared__ float g0[HH];
    __shared__ float t1[HH];
    const int b = blockIdx.x, c = threadIdx.x;
    const float* pb = pool + (size_t)b * 8 * 2 * HH;

    float s = 0.f, m = -3.4e38f;
#pragma unroll
    for (int seg = 0; seg < 8; seg++) {
        s += pb[seg * 2 * HH + c];
        m = fmaxf(m, pb[seg * 2 * HH + HH + c]);
    }
    g0[c] = s * (1.0f / NN) + m;
    __syncthreads();

    float a = b1[c];
#pragma unroll 4
    for (int k = 0; k < HH; k++) a += g0[k] * W1[k * HH + c];
    t1[c] = fmaxf(a, 0.f);
    __syncthreads();

    float a2 = b2[c];
#pragma unroll 4
    for (int k = 0; k < HH; k++) a2 += t1[k] * W2[k * HH + c];
    gout[b * HH + c] = a2;
}

// ---------------- launch ----------------
extern "C" void kernel_launch(void* const* d_in, const int* in_sizes, int n_in,
                              void* d_out, int out_size)
{
    const float* nf   = (const float*)d_in[0];
    const float* adj  = (const float*)d_in[1];
    const float* embW = (const float*)d_in[2];
    const float* embB = (const float*)d_in[3];
    const float* W0   = (const float*)d_in[4];
    const float* a10  = (const float*)d_in[5];
    const float* a20  = (const float*)d_in[6];
    const float* W1   = (const float*)d_in[7];
    const float* a11  = (const float*)d_in[8];
    const float* a21  = (const float*)d_in[9];
    const float* gW1  = (const float*)d_in[10];
    const float* gb1  = (const float*)d_in[11];
    const float* gW2  = (const float*)d_in[12];
    const float* gb2  = (const float*)d_in[13];

    float* out  = (float*)d_out;
    float* xout = out;                              // [B,N,H]
    float* gout = out + (size_t)BB * NN * HH;       // [B,H]

    float *xb, *hb, *s1b, *s2b, *poolb;
    uint32_t* maskb;
    cudaGetSymbolAddress((void**)&xb,    g_x);
    cudaGetSymbolAddress((void**)&hb,    g_h);
    cudaGetSymbolAddress((void**)&s1b,   g_s1);
    cudaGetSymbolAddress((void**)&s2b,   g_s2);
    cudaGetSymbolAddress((void**)&maskb, g_mask);
    cudaGetSymbolAddress((void**)&poolb, g_pool);

    cudaFuncSetAttribute(att_kernel, cudaFuncAttributeMaxDynamicSharedMemorySize, 64 * 1024);

    const int mrows = BB * NN;
    dim3 blk128(128);

    pack_adj_kernel<<<BB * NN * NN / 256, 256>>>(adj, maskb);
    embed_kernel<<<mrows / 16, blk128>>>(nf, embW, embB, xb);

    // layer 0
    gemm_s1s2_kernel<<<mrows / 16, blk128>>>(xb, W0, a10, a20, hb, s1b, s2b);
    att_kernel<<<dim3(NN / 16, BB), blk128, 64 * 1024>>>(maskb, hb, s1b, s2b, xb);

    // layer 1
    gemm_s1s2_kernel<<<mrows / 16, blk128>>>(xb, W1, a11, a21, hb, s1b, s2b);
    att_kernel<<<dim3(NN / 16, BB), blk128, 64 * 1024>>>(maskb, hb, s1b, s2b, xout);

    // pooling + MLP head
    pool_partial_kernel<<<dim3(8, BB), 256>>>(xout, poolb);
    mlp_kernel<<<BB, 256>>>(poolb, gW1, gb1, gW2, gb2, gout);
}

// round 9
// speedup vs baseline: 1.1433x; 1.0388x over previous
#include <cuda_runtime.h>
#include <cstdint>

#define BB 16
#define NN 1024
#define FIN 64
#define HH 256

// ---------------- scratch (no allocs allowed) ----------------
__device__ float g_x[BB * NN * HH];   // 16 MB
__device__ float g_h[BB * NN * HH];   // 16 MB
__device__ float g_s1[BB * NN];
__device__ float g_s2[BB * NN];
__device__ uint32_t g_mask[BB * NN * (NN / 32)];   // 2 MB bit-packed adj
__device__ float g_pool[BB * 8 * 2 * HH];          // pooling partials

typedef unsigned long long u64;

__device__ __forceinline__ u64 pack2(float x) {
    u64 r; asm("mov.b64 %0, {%1, %1};" : "=l"(r) : "f"(x)); return r;
}
__device__ __forceinline__ void ffma2(u64& d, u64 a, u64 b) {
    asm("fma.rn.f32x2 %0, %1, %2, %0;" : "+l"(d) : "l"(a), "l"(b));
}
__device__ __forceinline__ float2 unpack2(u64 v) {
    float2 r; asm("mov.b64 {%0, %1}, %2;" : "=f"(r.x), "=f"(r.y) : "l"(v)); return r;
}
__device__ __forceinline__ float leaky(float x) { return x >= 0.f ? x : 0.2f * x; }

// ============================================================================
// pack_adj: adj float(0/1)[B*N*N] -> bitmask (1 bit per entry)
// ============================================================================
__global__ __launch_bounds__(256) void pack_adj_kernel(
    const float* __restrict__ adj, uint32_t* __restrict__ mask)
{
    const int idx = blockIdx.x * 256 + threadIdx.x;
    const float v = adj[idx];
    const unsigned bal = __ballot_sync(0xffffffffu, v > 0.f);
    if ((threadIdx.x & 31) == 0) mask[idx >> 5] = bal;
}

// ============================================================================
// embed: out[M,256] = nf[M,64] @ W[64,256] + b
// ============================================================================
__global__ __launch_bounds__(128) void embed_kernel(
    const float* __restrict__ nf, const float* __restrict__ W,
    const float* __restrict__ bias, float* __restrict__ out)
{
    __shared__ float xs[4 * FIN * 4];
    const int row0 = blockIdx.x * 16;
    const int tid = threadIdx.x;

#pragma unroll
    for (int it = 0; it < 2; it++) {
        int idx = it * 128 + tid;
        int g = idx >> 6, k = idx & 63;
        float4 v;
        v.x = nf[(size_t)(row0 + 4 * g + 0) * FIN + k];
        v.y = nf[(size_t)(row0 + 4 * g + 1) * FIN + k];
        v.z = nf[(size_t)(row0 + 4 * g + 2) * FIN + k];
        v.w = nf[(size_t)(row0 + 4 * g + 3) * FIN + k];
        *(float4*)(xs + g * (FIN * 4) + k * 4) = v;
    }
    __syncthreads();

    u64 accA[8], accB[8];
#pragma unroll
    for (int p = 0; p < 8; p++) { accA[p] = 0ULL; accB[p] = 0ULL; }

    const int c = tid;
    float wA[4], wB[4];
#pragma unroll
    for (int u = 0; u < 4; u++) { wA[u] = W[u * HH + c]; wB[u] = W[u * HH + c + 128]; }

    for (int kt = 0; kt < FIN; kt += 4) {
        float cAv[4], cBv[4];
#pragma unroll
        for (int u = 0; u < 4; u++) { cAv[u] = wA[u]; cBv[u] = wB[u]; }
        if (kt + 4 < FIN) {
#pragma unroll
            for (int u = 0; u < 4; u++) {
                wA[u] = W[(kt + 4 + u) * HH + c];
                wB[u] = W[(kt + 4 + u) * HH + c + 128];
            }
        }
#pragma unroll
        for (int u = 0; u < 4; u++) {
            int k = kt + u;
            u64 h2a = pack2(cAv[u]);
            u64 h2b = pack2(cBv[u]);
#pragma unroll
            for (int g = 0; g < 4; g++) {
                ulonglong2 q = *(const ulonglong2*)(xs + g * (FIN * 4) + k * 4);
                ffma2(accA[2 * g], q.x, h2a); ffma2(accA[2 * g + 1], q.y, h2a);
                ffma2(accB[2 * g], q.x, h2b); ffma2(accB[2 * g + 1], q.y, h2b);
            }
        }
    }
    const float bA = bias[c], bBv = bias[c + 128];
    float* ob = out + (size_t)row0 * HH + c;
#pragma unroll
    for (int p = 0; p < 8; p++) {
        float2 vA = unpack2(accA[p]);
        float2 vB = unpack2(accB[p]);
        ob[(size_t)(2 * p) * HH]           = vA.x + bA;
        ob[(size_t)(2 * p + 1) * HH]       = vA.y + bA;
        ob[(size_t)(2 * p) * HH + 128]     = vB.x + bBv;
        ob[(size_t)(2 * p + 1) * HH + 128] = vB.y + bBv;
    }
}

// ============================================================================
// gemm256 + fused s1/s2
// ============================================================================
__global__ __launch_bounds__(128) void gemm_s1s2_kernel(
    const float* __restrict__ X, const float* __restrict__ W,
    const float* __restrict__ a1, const float* __restrict__ a2,
    float* __restrict__ hout, float* __restrict__ s1o, float* __restrict__ s2o)
{
    __shared__ float xs[4 * HH * 4];
    __shared__ float red[128];
    const int row0 = blockIdx.x * 16;
    const int tid = threadIdx.x;
    const int lane = tid & 31, wid = tid >> 5;

#pragma unroll
    for (int it = 0; it < 8; it++) {
        int idx = it * 128 + tid;
        int g = idx >> 8, k = idx & 255;
        float4 v;
        v.x = X[(size_t)(row0 + 4 * g + 0) * HH + k];
        v.y = X[(size_t)(row0 + 4 * g + 1) * HH + k];
        v.z = X[(size_t)(row0 + 4 * g + 2) * HH + k];
        v.w = X[(size_t)(row0 + 4 * g + 3) * HH + k];
        *(float4*)(xs + g * (HH * 4) + k * 4) = v;
    }
    __syncthreads();

    u64 accA[8], accB[8];
#pragma unroll
    for (int p = 0; p < 8; p++) { accA[p] = 0ULL; accB[p] = 0ULL; }

    const int c = tid;
    float wA[4], wB[4];
#pragma unroll
    for (int u = 0; u < 4; u++) { wA[u] = W[u * HH + c]; wB[u] = W[u * HH + c + 128]; }

    for (int kt = 0; kt < HH; kt += 4) {
        float cAv[4], cBv[4];
#pragma unroll
        for (int u = 0; u < 4; u++) { cAv[u] = wA[u]; cBv[u] = wB[u]; }
        if (kt + 4 < HH) {
#pragma unroll
            for (int u = 0; u < 4; u++) {
                wA[u] = W[(kt + 4 + u) * HH + c];
                wB[u] = W[(kt + 4 + u) * HH + c + 128];
            }
        }
#pragma unroll
        for (int u = 0; u < 4; u++) {
            int k = kt + u;
            u64 h2a = pack2(cAv[u]);
            u64 h2b = pack2(cBv[u]);
#pragma unroll
            for (int g = 0; g < 4; g++) {
                ulonglong2 q = *(const ulonglong2*)(xs + g * (HH * 4) + k * 4);
                ffma2(accA[2 * g], q.x, h2a); ffma2(accA[2 * g + 1], q.y, h2a);
                ffma2(accB[2 * g], q.x, h2b); ffma2(accB[2 * g + 1], q.y, h2b);
            }
        }
    }

    const float a1A = a1[c], a1B = a1[c + 128];
    const float a2A = a2[c], a2B = a2[c + 128];
    float s1p[16], s2p[16];
    float* ob = hout + (size_t)row0 * HH + c;
#pragma unroll
    for (int p = 0; p < 8; p++) {
        float2 vA = unpack2(accA[p]);
        float2 vB = unpack2(accB[p]);
        ob[(size_t)(2 * p) * HH]           = vA.x;
        ob[(size_t)(2 * p + 1) * HH]       = vA.y;
        ob[(size_t)(2 * p) * HH + 128]     = vB.x;
        ob[(size_t)(2 * p + 1) * HH + 128] = vB.y;
        s1p[2 * p]     = vA.x * a1A + vB.x * a1B;
        s1p[2 * p + 1] = vA.y * a1A + vB.y * a1B;
        s2p[2 * p]     = vA.x * a2A + vB.x * a2B;
        s2p[2 * p + 1] = vA.y * a2A + vB.y * a2B;
    }
#pragma unroll
    for (int r = 0; r < 16; r++) {
#pragma unroll
        for (int o = 16; o; o >>= 1) {
            s1p[r] += __shfl_xor_sync(0xffffffffu, s1p[r], o);
            s2p[r] += __shfl_xor_sync(0xffffffffu, s2p[r], o);
        }
        if (lane == 0) { red[r * 4 + wid] = s1p[r]; red[64 + r * 4 + wid] = s2p[r]; }
    }
    __syncthreads();
    if (tid < 32) {
        int r = tid & 15;
        int base = (tid < 16) ? 0 : 64;
        float s = red[base + r * 4] + red[base + r * 4 + 1] + red[base + r * 4 + 2] + red[base + r * 4 + 3];
        if (tid < 16) s1o[row0 + r] = s; else s2o[row0 + r] = s;
    }
}

// ============================================================================
// attention: out = relu( softmax_row( mask( leaky(s1_i + s2_j) ) ) @ h )
// 16 rows/block, 256 threads (8 warps). Phase B: warp = (8-row group, wid&1)
// x (64-col quarter, wid>>1); lane owns 2 cols. Per warp-j: 2 broadcast
// LDS.128 + 1 LDG.64 + 8 FFMA2. att smem [g][j][quad] (64 KB), 3 blocks/SM
// -> 24 warps/SM.
// ============================================================================
__global__ __launch_bounds__(256, 3) void att_kernel(
    const uint32_t* __restrict__ mask, const float* __restrict__ h,
    const float* __restrict__ s1, const float* __restrict__ s2,
    float* __restrict__ out)
{
    extern __shared__ float att[];        // 16384 floats (64KB)
    __shared__ uint32_t msk[16 * 32];     // 2KB: 16 rows x 32 words
    __shared__ float red[128];            // 16 rows x 8 warps
    __shared__ float rinv[16];
    __shared__ float s2mx[8];
    __shared__ float s2max_sh;

    const int b = blockIdx.y;
    const int i0 = blockIdx.x * 16;
    const int tid = threadIdx.x;
    const int lane = tid & 31, wid = tid >> 5;

    // load this block's 16 mask rows (512 words, 256 threads -> uint2 each)
    {
        const uint2* mg = (const uint2*)(mask + ((size_t)b * NN + i0) * 32);
        ((uint2*)msk)[tid] = mg[tid];
    }

    const float* s2b = s2 + b * NN;
    float s2v[4];
    float m = -3.4e38f;
#pragma unroll
    for (int u = 0; u < 4; u++) { s2v[u] = s2b[u * 256 + tid]; m = fmaxf(m, s2v[u]); }
#pragma unroll
    for (int o = 16; o; o >>= 1) m = fmaxf(m, __shfl_xor_sync(0xffffffffu, m, o));
    if (lane == 0) s2mx[wid] = m;
    __syncthreads();
    if (tid == 0) {
        float mm = s2mx[0];
#pragma unroll
        for (int w = 1; w < 8; w++) mm = fmaxf(mm, s2mx[w]);
        s2max_sh = mm;
    }
    __syncthreads();
    const float s2max = s2max_sh;

    // -------- phase A: unnormalized probs into att, rowsum partials --------
#pragma unroll
    for (int g = 0; g < 4; g++) {
        float s1v[4], mi[4], sum[4];
#pragma unroll
        for (int q = 0; q < 4; q++) {
            s1v[q] = s1[b * NN + i0 + 4 * g + q];
            mi[q] = leaky(s1v[q] + s2max);
            sum[q] = 0.f;
        }
#pragma unroll
        for (int u = 0; u < 4; u++) {
            int j = u * 256 + tid;
            float s2j = s2v[u];
            float4 pv;
#pragma unroll
            for (int q = 0; q < 4; q++) {
                uint32_t mw = msk[(4 * g + q) * 32 + u * 8 + wid];  // broadcast LDS
                float e = leaky(s1v[q] + s2j);
                float p = ((mw >> lane) & 1u) ? __expf(e - mi[q]) : 0.f;
                ((float*)&pv)[q] = p;
                sum[q] += p;
            }
            *(float4*)(att + g * 4096 + j * 4) = pv;   // conflict-free STS.128
        }
#pragma unroll
        for (int q = 0; q < 4; q++) {
#pragma unroll
            for (int o = 16; o; o >>= 1) sum[q] += __shfl_xor_sync(0xffffffffu, sum[q], o);
            if (lane == 0) red[(4 * g + q) * 8 + wid] = sum[q];
        }
    }
    __syncthreads();
    if (tid < 16) {
        float s = 0.f;
#pragma unroll
        for (int w = 0; w < 8; w++) s += red[tid * 8 + w];
        rinv[tid] = 1.0f / s;
    }
    __syncthreads();

    // -------- phase B: C[16,256] = att[16,1024] @ h[1024,256] --------
    // warp: rows rg*8..rg*8+7 (att quads 2rg, 2rg+1), cols qtr*64 + lane*2
    const int rg = wid & 1;
    const int qtr = wid >> 1;

    u64 acc[4][2];   // [row-pair][col]; row-pair rp = rows rg*8+2rp, +1
#pragma unroll
    for (int rp = 0; rp < 4; rp++) { acc[rp][0] = 0ULL; acc[rp][1] = 0ULL; }

    const float* hp = h + (size_t)b * NN * HH + qtr * 64 + lane * 2;
    const float* aq0p = att + (2 * rg) * 4096;
    const float* aq1p = aq0p + 4096;

    float2 hbuf[8];
#pragma unroll
    for (int u = 0; u < 8; u++) hbuf[u] = *(const float2*)(hp + (size_t)u * HH);

    for (int jt = 0; jt < NN; jt += 8) {
        const bool pf = (jt + 8) < NN;
#pragma unroll
        for (int u = 0; u < 8; u++) {
            const int j = jt + u;
            float2 hv = hbuf[u];
            if (pf) hbuf[u] = *(const float2*)(hp + (size_t)(jt + 8 + u) * HH);
            ulonglong2 aq0 = *(const ulonglong2*)(aq0p + j * 4);  // rows (8rg,+1),(+2,+3)
            ulonglong2 aq1 = *(const ulonglong2*)(aq1p + j * 4);  // rows (+4,+5),(+6,+7)
            u64 h0 = pack2(hv.x), h1 = pack2(hv.y);
            ffma2(acc[0][0], aq0.x, h0); ffma2(acc[0][1], aq0.x, h1);
            ffma2(acc[1][0], aq0.y, h0); ffma2(acc[1][1], aq0.y, h1);
            ffma2(acc[2][0], aq1.x, h0); ffma2(acc[2][1], aq1.x, h1);
            ffma2(acc[3][0], aq1.y, h0); ffma2(acc[3][1], aq1.y, h1);
        }
    }

    // epilogue: rows rg*8+2rp (+1), cols qtr*64 + lane*2 (float2 stores)
    float* ob = out + ((size_t)b * NN + i0 + rg * 8) * HH + qtr * 64 + lane * 2;
#pragma unroll
    for (int rp = 0; rp < 4; rp++) {
        const float ri0 = rinv[rg * 8 + 2 * rp];
        const float ri1 = rinv[rg * 8 + 2 * rp + 1];
        float2 c0 = unpack2(acc[rp][0]);   // (row0, row1) at col+0
        float2 c1 = unpack2(acc[rp][1]);   // (row0, row1) at col+1
        float2 r0v, r1v;
        r0v.x = fmaxf(c0.x * ri0, 0.f); r0v.y = fmaxf(c1.x * ri0, 0.f);
        r1v.x = fmaxf(c0.y * ri1, 0.f); r1v.y = fmaxf(c1.y * ri1, 0.f);
        *(float2*)(ob + (size_t)(2 * rp) * HH)     = r0v;
        *(float2*)(ob + (size_t)(2 * rp + 1) * HH) = r1v;
    }
}

// ---------------- pooling partials: 8 segments of 128 rows ----------------
__global__ __launch_bounds__(256) void pool_partial_kernel(
    const float* __restrict__ x, float* __restrict__ pool)
{
    const int seg = blockIdx.x, b = blockIdx.y, c = threadIdx.x;
    const float* xb = x + ((size_t)b * NN + seg * 128) * HH + c;
    float s = 0.f, m = -3.4e38f;
#pragma unroll 8
    for (int n = 0; n < 128; n++) {
        float v = xb[(size_t)n * HH];
        s += v;
        m = fmaxf(m, v);
    }
    float* pb = pool + ((size_t)b * 8 + seg) * 2 * HH;
    pb[c] = s;
    pb[HH + c] = m;
}

// ---------------- combine + 2-layer MLP ----------------
__global__ __launch_bounds__(256) void mlp_kernel(
    const float* __restrict__ pool, const float* __restrict__ W1,
    const float* __restrict__ b1, const float* __restrict__ W2,
    const float* __restrict__ b2, float* __restrict__ gout)
{
    __shared__ float g0[HH];
    __shared__ float t1[HH];
    const int b = blockIdx.x, c = threadIdx.x;
    const float* pb = pool + (size_t)b * 8 * 2 * HH;

    float s = 0.f, m = -3.4e38f;
#pragma unroll
    for (int seg = 0; seg < 8; seg++) {
        s += pb[seg * 2 * HH + c];
        m = fmaxf(m, pb[seg * 2 * HH + HH + c]);
    }
    g0[c] = s * (1.0f / NN) + m;
    __syncthreads();

    float a = b1[c];
#pragma unroll 4
    for (int k = 0; k < HH; k++) a += g0[k] * W1[k * HH + c];
    t1[c] = fmaxf(a, 0.f);
    __syncthreads();

    float a2 = b2[c];
#pragma unroll 4
    for (int k = 0; k < HH; k++) a2 += t1[k] * W2[k * HH + c];
    gout[b * HH + c] = a2;
}

// ---------------- launch ----------------
extern "C" void kernel_launch(void* const* d_in, const int* in_sizes, int n_in,
                              void* d_out, int out_size)
{
    const float* nf   = (const float*)d_in[0];
    const float* adj  = (const float*)d_in[1];
    const float* embW = (const float*)d_in[2];
    const float* embB = (const float*)d_in[3];
    const float* W0   = (const float*)d_in[4];
    const float* a10  = (const float*)d_in[5];
    const float* a20  = (const float*)d_in[6];
    const float* W1   = (const float*)d_in[7];
    const float* a11  = (const float*)d_in[8];
    const float* a21  = (const float*)d_in[9];
    const float* gW1  = (const float*)d_in[10];
    const float* gb1  = (const float*)d_in[11];
    const float* gW2  = (const float*)d_in[12];
    const float* gb2  = (const float*)d_in[13];

    float* out  = (float*)d_out;
    float* xout = out;                              // [B,N,H]
    float* gout = out + (size_t)BB * NN * HH;       // [B,H]

    float *xb, *hb, *s1b, *s2b, *poolb;
    uint32_t* maskb;
    cudaGetSymbolAddress((void**)&xb,    g_x);
    cudaGetSymbolAddress((void**)&hb,    g_h);
    cudaGetSymbolAddress((void**)&s1b,   g_s1);
    cudaGetSymbolAddress((void**)&s2b,   g_s2);
    cudaGetSymbolAddress((void**)&maskb, g_mask);
    cudaGetSymbolAddress((void**)&poolb, g_pool);

    cudaFuncSetAttribute(att_kernel, cudaFuncAttributeMaxDynamicSharedMemorySize, 64 * 1024);

    const int mrows = BB * NN;
    dim3 blk128(128);

    pack_adj_kernel<<<BB * NN * NN / 256, 256>>>(adj, maskb);
    embed_kernel<<<mrows / 16, blk128>>>(nf, embW, embB, xb);

    // layer 0
    gemm_s1s2_kernel<<<mrows / 16, blk128>>>(xb, W0, a10, a20, hb, s1b, s2b);
    att_kernel<<<dim3(NN / 16, BB), 256, 64 * 1024>>>(maskb, hb, s1b, s2b, xb);

    // layer 1
    gemm_s1s2_kernel<<<mrows / 16, blk128>>>(xb, W1, a11, a21, hb, s1b, s2b);
    att_kernel<<<dim3(NN / 16, BB), 256, 64 * 1024>>>(maskb, hb, s1b, s2b, xout);

    // pooling + MLP head
    pool_partial_kernel<<<dim3(8, BB), 256>>>(xout, poolb);
    mlp_kernel<<<BB, 256>>>(poolb, gW1, gb1, gW2, gb2, gout);
}

// round 10
// speedup vs baseline: 1.1741x; 1.0270x over previous
#include <cuda_runtime.h>
#include <cstdint>

#define BB 16
#define NN 1024
#define FIN 64
#define HH 256

// ---------------- scratch (no allocs allowed) ----------------
__device__ float g_x[BB * NN * HH];   // 16 MB
__device__ float g_h[BB * NN * HH];   // 16 MB
__device__ float g_s1[BB * NN];
__device__ float g_s2[BB * NN];
__device__ uint32_t g_mask[BB * NN * (NN / 32)];   // 2 MB bit-packed adj
__device__ float g_pool[BB * 8 * 2 * HH];          // pooling partials

typedef unsigned long long u64;

__device__ __forceinline__ u64 pack2(float x) {
    u64 r; asm("mov.b64 %0, {%1, %1};" : "=l"(r) : "f"(x)); return r;
}
__device__ __forceinline__ void ffma2(u64& d, u64 a, u64 b) {
    asm("fma.rn.f32x2 %0, %1, %2, %0;" : "+l"(d) : "l"(a), "l"(b));
}
__device__ __forceinline__ float2 unpack2(u64 v) {
    float2 r; asm("mov.b64 {%0, %1}, %2;" : "=f"(r.x), "=f"(r.y) : "l"(v)); return r;
}
__device__ __forceinline__ float leaky(float x) { return x >= 0.f ? x : 0.2f * x; }

// ============================================================================
// pack_adj: adj float(0/1)[B*N*N] -> bitmask (1 bit per entry)
// ============================================================================
__global__ __launch_bounds__(256) void pack_adj_kernel(
    const float* __restrict__ adj, uint32_t* __restrict__ mask)
{
    const int idx = blockIdx.x * 256 + threadIdx.x;
    const float v = adj[idx];
    const unsigned bal = __ballot_sync(0xffffffffu, v > 0.f);
    if ((threadIdx.x & 31) == 0) mask[idx >> 5] = bal;
}

// ============================================================================
// embed: out[M,256] = nf[M,64] @ W[64,256] + b
// ============================================================================
__global__ __launch_bounds__(128) void embed_kernel(
    const float* __restrict__ nf, const float* __restrict__ W,
    const float* __restrict__ bias, float* __restrict__ out)
{
    __shared__ float xs[4 * FIN * 4];
    const int row0 = blockIdx.x * 16;
    const int tid = threadIdx.x;

#pragma unroll
    for (int it = 0; it < 2; it++) {
        int idx = it * 128 + tid;
        int g = idx >> 6, k = idx & 63;
        float4 v;
        v.x = nf[(size_t)(row0 + 4 * g + 0) * FIN + k];
        v.y = nf[(size_t)(row0 + 4 * g + 1) * FIN + k];
        v.z = nf[(size_t)(row0 + 4 * g + 2) * FIN + k];
        v.w = nf[(size_t)(row0 + 4 * g + 3) * FIN + k];
        *(float4*)(xs + g * (FIN * 4) + k * 4) = v;
    }
    __syncthreads();

    u64 accA[8], accB[8];
#pragma unroll
    for (int p = 0; p < 8; p++) { accA[p] = 0ULL; accB[p] = 0ULL; }

    const int c = tid;
    float wA[4], wB[4];
#pragma unroll
    for (int u = 0; u < 4; u++) { wA[u] = W[u * HH + c]; wB[u] = W[u * HH + c + 128]; }

    for (int kt = 0; kt < FIN; kt += 4) {
        float cAv[4], cBv[4];
#pragma unroll
        for (int u = 0; u < 4; u++) { cAv[u] = wA[u]; cBv[u] = wB[u]; }
        if (kt + 4 < FIN) {
#pragma unroll
            for (int u = 0; u < 4; u++) {
                wA[u] = W[(kt + 4 + u) * HH + c];
                wB[u] = W[(kt + 4 + u) * HH + c + 128];
            }
        }
#pragma unroll
        for (int u = 0; u < 4; u++) {
            int k = kt + u;
            u64 h2a = pack2(cAv[u]);
            u64 h2b = pack2(cBv[u]);
#pragma unroll
            for (int g = 0; g < 4; g++) {
                ulonglong2 q = *(const ulonglong2*)(xs + g * (FIN * 4) + k * 4);
                ffma2(accA[2 * g], q.x, h2a); ffma2(accA[2 * g + 1], q.y, h2a);
                ffma2(accB[2 * g], q.x, h2b); ffma2(accB[2 * g + 1], q.y, h2b);
            }
        }
    }
    const float bA = bias[c], bBv = bias[c + 128];
    float* ob = out + (size_t)row0 * HH + c;
#pragma unroll
    for (int p = 0; p < 8; p++) {
        float2 vA = unpack2(accA[p]);
        float2 vB = unpack2(accB[p]);
        ob[(size_t)(2 * p) * HH]           = vA.x + bA;
        ob[(size_t)(2 * p + 1) * HH]       = vA.y + bA;
        ob[(size_t)(2 * p) * HH + 128]     = vB.x + bBv;
        ob[(size_t)(2 * p + 1) * HH + 128] = vB.y + bBv;
    }
}

// ============================================================================
// gemm256 + fused s1/s2
// ============================================================================
__global__ __launch_bounds__(128) void gemm_s1s2_kernel(
    const float* __restrict__ X, const float* __restrict__ W,
    const float* __restrict__ a1, const float* __restrict__ a2,
    float* __restrict__ hout, float* __restrict__ s1o, float* __restrict__ s2o)
{
    __shared__ float xs[4 * HH * 4];
    __shared__ float red[128];
    const int row0 = blockIdx.x * 16;
    const int tid = threadIdx.x;
    const int lane = tid & 31, wid = tid >> 5;

#pragma unroll
    for (int it = 0; it < 8; it++) {
        int idx = it * 128 + tid;
        int g = idx >> 8, k = idx & 255;
        float4 v;
        v.x = X[(size_t)(row0 + 4 * g + 0) * HH + k];
        v.y = X[(size_t)(row0 + 4 * g + 1) * HH + k];
        v.z = X[(size_t)(row0 + 4 * g + 2) * HH + k];
        v.w = X[(size_t)(row0 + 4 * g + 3) * HH + k];
        *(float4*)(xs + g * (HH * 4) + k * 4) = v;
    }
    __syncthreads();

    u64 accA[8], accB[8];
#pragma unroll
    for (int p = 0; p < 8; p++) { accA[p] = 0ULL; accB[p] = 0ULL; }

    const int c = tid;
    float wA[4], wB[4];
#pragma unroll
    for (int u = 0; u < 4; u++) { wA[u] = W[u * HH + c]; wB[u] = W[u * HH + c + 128]; }

    for (int kt = 0; kt < HH; kt += 4) {
        float cAv[4], cBv[4];
#pragma unroll
        for (int u = 0; u < 4; u++) { cAv[u] = wA[u]; cBv[u] = wB[u]; }
        if (kt + 4 < HH) {
#pragma unroll
            for (int u = 0; u < 4; u++) {
                wA[u] = W[(kt + 4 + u) * HH + c];
                wB[u] = W[(kt + 4 + u) * HH + c + 128];
            }
        }
#pragma unroll
        for (int u = 0; u < 4; u++) {
            int k = kt + u;
            u64 h2a = pack2(cAv[u]);
            u64 h2b = pack2(cBv[u]);
#pragma unroll
            for (int g = 0; g < 4; g++) {
                ulonglong2 q = *(const ulonglong2*)(xs + g * (HH * 4) + k * 4);
                ffma2(accA[2 * g], q.x, h2a); ffma2(accA[2 * g + 1], q.y, h2a);
                ffma2(accB[2 * g], q.x, h2b); ffma2(accB[2 * g + 1], q.y, h2b);
            }
        }
    }

    const float a1A = a1[c], a1B = a1[c + 128];
    const float a2A = a2[c], a2B = a2[c + 128];
    float s1p[16], s2p[16];
    float* ob = hout + (size_t)row0 * HH + c;
#pragma unroll
    for (int p = 0; p < 8; p++) {
        float2 vA = unpack2(accA[p]);
        float2 vB = unpack2(accB[p]);
        ob[(size_t)(2 * p) * HH]           = vA.x;
        ob[(size_t)(2 * p + 1) * HH]       = vA.y;
        ob[(size_t)(2 * p) * HH + 128]     = vB.x;
        ob[(size_t)(2 * p + 1) * HH + 128] = vB.y;
        s1p[2 * p]     = vA.x * a1A + vB.x * a1B;
        s1p[2 * p + 1] = vA.y * a1A + vB.y * a1B;
        s2p[2 * p]     = vA.x * a2A + vB.x * a2B;
        s2p[2 * p + 1] = vA.y * a2A + vB.y * a2B;
    }
#pragma unroll
    for (int r = 0; r < 16; r++) {
#pragma unroll
        for (int o = 16; o; o >>= 1) {
            s1p[r] += __shfl_xor_sync(0xffffffffu, s1p[r], o);
            s2p[r] += __shfl_xor_sync(0xffffffffu, s2p[r], o);
        }
        if (lane == 0) { red[r * 4 + wid] = s1p[r]; red[64 + r * 4 + wid] = s2p[r]; }
    }
    __syncthreads();
    if (tid < 32) {
        int r = tid & 15;
        int base = (tid < 16) ? 0 : 64;
        float s = red[base + r * 4] + red[base + r * 4 + 1] + red[base + r * 4 + 2] + red[base + r * 4 + 3];
        if (tid < 16) s1o[row0 + r] = s; else s2o[row0 + r] = s;
    }
}

// ============================================================================
// attention: out = relu( softmax_row( mask( leaky(s1_i + s2_j) ) ) @ h )
// 16 rows/block, 256 threads. Phase B: warp = ALL 16 rows x 128-col half
// (half = wid&1), 4-way j-split (jseg = wid>>1, 256 j each); lane owns 4
// consecutive cols. Per warp-j: 4 broadcast LDS.128 + 1 LDG.128 + 32 FFMA2.
// Cross-jseg partials reduced through the att smem buffer at the end.
// ============================================================================
__global__ __launch_bounds__(256, 2) void att_kernel(
    const uint32_t* __restrict__ mask, const float* __restrict__ h,
    const float* __restrict__ s1, const float* __restrict__ s2,
    float* __restrict__ out)
{
    extern __shared__ float att[];        // 16384 floats (64KB); reused for partials
    __shared__ uint32_t msk[16 * 32];     // 2KB: 16 rows x 32 words
    __shared__ float red[128];            // 16 rows x 8 warps
    __shared__ float rinv[16];
    __shared__ float s2mx[8];
    __shared__ float s2max_sh;

    const int b = blockIdx.y;
    const int i0 = blockIdx.x * 16;
    const int tid = threadIdx.x;
    const int lane = tid & 31, wid = tid >> 5;

    // load this block's 16 mask rows (512 words, 256 threads -> uint2 each)
    {
        const uint2* mg = (const uint2*)(mask + ((size_t)b * NN + i0) * 32);
        ((uint2*)msk)[tid] = mg[tid];
    }

    const float* s2b = s2 + b * NN;
    float s2v[4];
    float m = -3.4e38f;
#pragma unroll
    for (int u = 0; u < 4; u++) { s2v[u] = s2b[u * 256 + tid]; m = fmaxf(m, s2v[u]); }
#pragma unroll
    for (int o = 16; o; o >>= 1) m = fmaxf(m, __shfl_xor_sync(0xffffffffu, m, o));
    if (lane == 0) s2mx[wid] = m;
    __syncthreads();
    if (tid == 0) {
        float mm = s2mx[0];
#pragma unroll
        for (int w = 1; w < 8; w++) mm = fmaxf(mm, s2mx[w]);
        s2max_sh = mm;
    }
    __syncthreads();
    const float s2max = s2max_sh;

    // -------- phase A: unnormalized probs into att, rowsum partials --------
#pragma unroll
    for (int g = 0; g < 4; g++) {
        float s1v[4], mi[4], sum[4];
#pragma unroll
        for (int q = 0; q < 4; q++) {
            s1v[q] = s1[b * NN + i0 + 4 * g + q];
            mi[q] = leaky(s1v[q] + s2max);
            sum[q] = 0.f;
        }
#pragma unroll
        for (int u = 0; u < 4; u++) {
            int j = u * 256 + tid;
            float s2j = s2v[u];
            float4 pv;
#pragma unroll
            for (int q = 0; q < 4; q++) {
                uint32_t mw = msk[(4 * g + q) * 32 + u * 8 + wid];  // broadcast LDS
                float e = leaky(s1v[q] + s2j);
                float p = ((mw >> lane) & 1u) ? __expf(e - mi[q]) : 0.f;
                ((float*)&pv)[q] = p;
                sum[q] += p;
            }
            *(float4*)(att + g * 4096 + j * 4) = pv;   // conflict-free STS.128
        }
#pragma unroll
        for (int q = 0; q < 4; q++) {
#pragma unroll
            for (int o = 16; o; o >>= 1) sum[q] += __shfl_xor_sync(0xffffffffu, sum[q], o);
            if (lane == 0) red[(4 * g + q) * 8 + wid] = sum[q];
        }
    }
    __syncthreads();
    if (tid < 16) {
        float s = 0.f;
#pragma unroll
        for (int w = 0; w < 8; w++) s += red[tid * 8 + w];
        rinv[tid] = 1.0f / s;
    }
    __syncthreads();

    // -------- phase B: partial C[16,128] per warp over its 256-j segment ----
    const int half = wid & 1;        // column half
    const int jseg = wid >> 1;       // j segment 0..3
    const int j0 = jseg * 256;

    u64 acc[8][4];                   // [row-pair][col]; rp -> rows 2rp, 2rp+1
#pragma unroll
    for (int rp = 0; rp < 8; rp++)
#pragma unroll
        for (int cc = 0; cc < 4; cc++) acc[rp][cc] = 0ULL;

    const float* hp = h + b * (NN * HH) + half * 128 + lane * 4;

    float4 hbuf[4];
#pragma unroll
    for (int u = 0; u < 4; u++) hbuf[u] = *(const float4*)(hp + (j0 + u) * HH);

    for (int jt = j0; jt < j0 + 252; jt += 4) {
#pragma unroll
        for (int u = 0; u < 4; u++) {
            const int j = jt + u;
            float4 hv = hbuf[u];
            hbuf[u] = *(const float4*)(hp + (j + 4) * HH);
            u64 h0 = pack2(hv.x), h1 = pack2(hv.y), h2 = pack2(hv.z), h3 = pack2(hv.w);
#pragma unroll
            for (int g = 0; g < 4; g++) {
                ulonglong2 aq = *(const ulonglong2*)(att + g * 4096 + j * 4);
                ffma2(acc[2 * g][0], aq.x, h0); ffma2(acc[2 * g][1], aq.x, h1);
                ffma2(acc[2 * g][2], aq.x, h2); ffma2(acc[2 * g][3], aq.x, h3);
                ffma2(acc[2 * g + 1][0], aq.y, h0); ffma2(acc[2 * g + 1][1], aq.y, h1);
                ffma2(acc[2 * g + 1][2], aq.y, h2); ffma2(acc[2 * g + 1][3], aq.y, h3);
            }
        }
    }
    // tail: last 4 j (no prefetch)
#pragma unroll
    for (int u = 0; u < 4; u++) {
        const int j = j0 + 252 + u;
        float4 hv = hbuf[u];
        u64 h0 = pack2(hv.x), h1 = pack2(hv.y), h2 = pack2(hv.z), h3 = pack2(hv.w);
#pragma unroll
        for (int g = 0; g < 4; g++) {
            ulonglong2 aq = *(const ulonglong2*)(att + g * 4096 + j * 4);
            ffma2(acc[2 * g][0], aq.x, h0); ffma2(acc[2 * g][1], aq.x, h1);
            ffma2(acc[2 * g][2], aq.x, h2); ffma2(acc[2 * g][3], aq.x, h3);
            ffma2(acc[2 * g + 1][0], aq.y, h0); ffma2(acc[2 * g + 1][1], aq.y, h1);
            ffma2(acc[2 * g + 1][2], aq.y, h2); ffma2(acc[2 * g + 1][3], aq.y, h3);
        }
    }

    // -------- reduce partials across jseg through smem (reuse att) --------
    __syncthreads();   // all warps done reading att
    {
        float* part = att + (jseg * 2 + half) * 2048;   // [16 rows][128 cols]
#pragma unroll
        for (int rp = 0; rp < 8; rp++) {
            float2 c0 = unpack2(acc[rp][0]);
            float2 c1 = unpack2(acc[rp][1]);
            float2 c2 = unpack2(acc[rp][2]);
            float2 c3 = unpack2(acc[rp][3]);
            float4 r0v = make_float4(c0.x, c1.x, c2.x, c3.x);
            float4 r1v = make_float4(c0.y, c1.y, c2.y, c3.y);
            *(float4*)(part + (2 * rp) * 128 + lane * 4)     = r0v;
            *(float4*)(part + (2 * rp + 1) * 128 + lane * 4) = r1v;
        }
    }
    __syncthreads();

    // combine: thread handles row r = tid>>4, col-quads qbase + {0,16,32,48}
    {
        const int r = tid >> 4;
        const int qbase = tid & 15;
        const float ri = rinv[r];
        float* ob = out + ((size_t)b * NN + i0 + r) * HH;
#pragma unroll
        for (int k = 0; k < 4; k++) {
            const int q = qbase + k * 16;          // quad 0..63, col = q*4
            const int hr = q >> 5;                 // which half
            const int cl = (q & 31) * 4;           // col within half
            float4 s = make_float4(0.f, 0.f, 0.f, 0.f);
#pragma unroll
            for (int js = 0; js < 4; js++) {
                float4 v = *(const float4*)(att + (js * 2 + hr) * 2048 + r * 128 + cl);
                s.x += v.x; s.y += v.y; s.z += v.z; s.w += v.w;
            }
            float4 o;
            o.x = fmaxf(s.x * ri, 0.f);
            o.y = fmaxf(s.y * ri, 0.f);
            o.z = fmaxf(s.z * ri, 0.f);
            o.w = fmaxf(s.w * ri, 0.f);
            *(float4*)(ob + q * 4) = o;
        }
    }
}

// ---------------- pooling partials: 8 segments of 128 rows ----------------
__global__ __launch_bounds__(256) void pool_partial_kernel(
    const float* __restrict__ x, float* __restrict__ pool)
{
    const int seg = blockIdx.x, b = blockIdx.y, c = threadIdx.x;
    const float* xb = x + ((size_t)b * NN + seg * 128) * HH + c;
    float s = 0.f, m = -3.4e38f;
#pragma unroll 8
    for (int n = 0; n < 128; n++) {
        float v = xb[(size_t)n * HH];
        s += v;
        m = fmaxf(m, v);
    }
    float* pb = pool + ((size_t)b * 8 + seg) * 2 * HH;
    pb[c] = s;
    pb[HH + c] = m;
}

// ---------------- combine + 2-layer MLP ----------------
__global__ __launch_bounds__(256) void mlp_kernel(
    const float* __restrict__ pool, const float* __restrict__ W1,
    const float* __restrict__ b1, const float* __restrict__ W2,
    const float* __restrict__ b2, float* __restrict__ gout)
{
    __shared__ float g0[HH];
    __shared__ float t1[HH];
    const int b = blockIdx.x, c = threadIdx.x;
    const float* pb = pool + (size_t)b * 8 * 2 * HH;

    float s = 0.f, m = -3.4e38f;
#pragma unroll
    for (int seg = 0; seg < 8; seg++) {
        s += pb[seg * 2 * HH + c];
        m = fmaxf(m, pb[seg * 2 * HH + HH + c]);
    }
    g0[c] = s * (1.0f / NN) + m;
    __syncthreads();

    float a = b1[c];
#pragma unroll 4
    for (int k = 0; k < HH; k++) a += g0[k] * W1[k * HH + c];
    t1[c] = fmaxf(a, 0.f);
    __syncthreads();

    float a2 = b2[c];
#pragma unroll 4
    for (int k = 0; k < HH; k++) a2 += t1[k] * W2[k * HH + c];
    gout[b * HH + c] = a2;
}

// ---------------- launch ----------------
extern "C" void kernel_launch(void* const* d_in, const int* in_sizes, int n_in,
                              void* d_out, int out_size)
{
    const float* nf   = (const float*)d_in[0];
    const float* adj  = (const float*)d_in[1];
    const float* embW = (const float*)d_in[2];
    const float* embB = (const float*)d_in[3];
    const float* W0   = (const float*)d_in[4];
    const float* a10  = (const float*)d_in[5];
    const float* a20  = (const float*)d_in[6];
    const float* W1   = (const float*)d_in[7];
    const float* a11  = (const float*)d_in[8];
    const float* a21  = (const float*)d_in[9];
    const float* gW1  = (const float*)d_in[10];
    const float* gb1  = (const float*)d_in[11];
    const float* gW2  = (const float*)d_in[12];
    const float* gb2  = (const float*)d_in[13];

    float* out  = (float*)d_out;
    float* xout = out;                              // [B,N,H]
    float* gout = out + (size_t)BB * NN * HH;       // [B,H]

    float *xb, *hb, *s1b, *s2b, *poolb;
    uint32_t* maskb;
    cudaGetSymbolAddress((void**)&xb,    g_x);
    cudaGetSymbolAddress((void**)&hb,    g_h);
    cudaGetSymbolAddress((void**)&s1b,   g_s1);
    cudaGetSymbolAddress((void**)&s2b,   g_s2);
    cudaGetSymbolAddress((void**)&maskb, g_mask);
    cudaGetSymbolAddress((void**)&poolb, g_pool);

    cudaFuncSetAttribute(att_kernel, cudaFuncAttributeMaxDynamicSharedMemorySize, 64 * 1024);

    const int mrows = BB * NN;
    dim3 blk128(128);

    pack_adj_kernel<<<BB * NN * NN / 256, 256>>>(adj, maskb);
    embed_kernel<<<mrows / 16, blk128>>>(nf, embW, embB, xb);

    // layer 0
    gemm_s1s2_kernel<<<mrows / 16, blk128>>>(xb, W0, a10, a20, hb, s1b, s2b);
    att_kernel<<<dim3(NN / 16, BB), 256, 64 * 1024>>>(maskb, hb, s1b, s2b, xb);

    // layer 1
    gemm_s1s2_kernel<<<mrows / 16, blk128>>>(xb, W1, a11, a21, hb, s1b, s2b);
    att_kernel<<<dim3(NN / 16, BB), 256, 64 * 1024>>>(maskb, hb, s1b, s2b, xout);

    // pooling + MLP head
    pool_partial_kernel<<<dim3(8, BB), 256>>>(xout, poolb);
    mlp_kernel<<<BB, 256>>>(poolb, gW1, gb1, gW2, gb2, gout);
}

// round 12
// speedup vs baseline: 1.3773x; 1.1730x over previous
#include <cuda_runtime.h>
#include <cstdint>

#define BB 16
#define NN 1024
#define FIN 64
#define HH 256

// ---------------- scratch (no allocs allowed) ----------------
__device__ float g_x[BB * NN * HH];   // 16 MB
__device__ float g_h[BB * NN * HH];   // 16 MB
__device__ float g_s1[BB * NN];
__device__ float g_s2[BB * NN];
__device__ uint32_t g_mask[BB * NN * (NN / 32)];   // 2 MB bit-packed adj
__device__ float g_pool[BB * 8 * 2 * HH];          // pooling partials

typedef unsigned long long u64;

__device__ __forceinline__ u64 pack2(float x) {
    u64 r; asm("mov.b64 %0, {%1, %1};" : "=l"(r) : "f"(x)); return r;
}
__device__ __forceinline__ void ffma2(u64& d, u64 a, u64 b) {
    asm("fma.rn.f32x2 %0, %1, %2, %0;" : "+l"(d) : "l"(a), "l"(b));
}
__device__ __forceinline__ float2 unpack2(u64 v) {
    float2 r; asm("mov.b64 {%0, %1}, %2;" : "=f"(r.x), "=f"(r.y) : "l"(v)); return r;
}
__device__ __forceinline__ float leaky(float x) { return x >= 0.f ? x : 0.2f * x; }

// ============================================================================
// pack_adj: adj float(0/1)[B*N*N] -> bitmask (1 bit per entry)
// ============================================================================
__global__ __launch_bounds__(256) void pack_adj_kernel(
    const float* __restrict__ adj, uint32_t* __restrict__ mask)
{
    const int idx = blockIdx.x * 256 + threadIdx.x;
    const float v = adj[idx];
    const unsigned bal = __ballot_sync(0xffffffffu, v > 0.f);
    if ((threadIdx.x & 31) == 0) mask[idx >> 5] = bal;
}

// ============================================================================
// embed: out[M,256] = nf[M,64] @ W[64,256] + b
// ============================================================================
__global__ __launch_bounds__(128) void embed_kernel(
    const float* __restrict__ nf, const float* __restrict__ W,
    const float* __restrict__ bias, float* __restrict__ out)
{
    __shared__ float xs[4 * FIN * 4];
    const int row0 = blockIdx.x * 16;
    const int tid = threadIdx.x;

#pragma unroll
    for (int it = 0; it < 2; it++) {
        int idx = it * 128 + tid;
        int g = idx >> 6, k = idx & 63;
        float4 v;
        v.x = nf[(size_t)(row0 + 4 * g + 0) * FIN + k];
        v.y = nf[(size_t)(row0 + 4 * g + 1) * FIN + k];
        v.z = nf[(size_t)(row0 + 4 * g + 2) * FIN + k];
        v.w = nf[(size_t)(row0 + 4 * g + 3) * FIN + k];
        *(float4*)(xs + g * (FIN * 4) + k * 4) = v;
    }
    __syncthreads();

    u64 accA[8], accB[8];
#pragma unroll
    for (int p = 0; p < 8; p++) { accA[p] = 0ULL; accB[p] = 0ULL; }

    const int c = tid;
    float wA[4], wB[4];
#pragma unroll
    for (int u = 0; u < 4; u++) { wA[u] = W[u * HH + c]; wB[u] = W[u * HH + c + 128]; }

    for (int kt = 0; kt < FIN; kt += 4) {
        float cAv[4], cBv[4];
#pragma unroll
        for (int u = 0; u < 4; u++) { cAv[u] = wA[u]; cBv[u] = wB[u]; }
        if (kt + 4 < FIN) {
#pragma unroll
            for (int u = 0; u < 4; u++) {
                wA[u] = W[(kt + 4 + u) * HH + c];
                wB[u] = W[(kt + 4 + u) * HH + c + 128];
            }
        }
#pragma unroll
        for (int u = 0; u < 4; u++) {
            int k = kt + u;
            u64 h2a = pack2(cAv[u]);
            u64 h2b = pack2(cBv[u]);
#pragma unroll
            for (int g = 0; g < 4; g++) {
                ulonglong2 q = *(const ulonglong2*)(xs + g * (FIN * 4) + k * 4);
                ffma2(accA[2 * g], q.x, h2a); ffma2(accA[2 * g + 1], q.y, h2a);
                ffma2(accB[2 * g], q.x, h2b); ffma2(accB[2 * g + 1], q.y, h2b);
            }
        }
    }
    const float bA = bias[c], bBv = bias[c + 128];
    float* ob = out + (size_t)row0 * HH + c;
#pragma unroll
    for (int p = 0; p < 8; p++) {
        float2 vA = unpack2(accA[p]);
        float2 vB = unpack2(accB[p]);
        ob[(size_t)(2 * p) * HH]           = vA.x + bA;
        ob[(size_t)(2 * p + 1) * HH]       = vA.y + bA;
        ob[(size_t)(2 * p) * HH + 128]     = vB.x + bBv;
        ob[(size_t)(2 * p + 1) * HH + 128] = vB.y + bBv;
    }
}

// ============================================================================
// gemm256 + fused s1/s2
// ============================================================================
__global__ __launch_bounds__(128) void gemm_s1s2_kernel(
    const float* __restrict__ X, const float* __restrict__ W,
    const float* __restrict__ a1, const float* __restrict__ a2,
    float* __restrict__ hout, float* __restrict__ s1o, float* __restrict__ s2o)
{
    __shared__ float xs[4 * HH * 4];
    __shared__ float red[128];
    const int row0 = blockIdx.x * 16;
    const int tid = threadIdx.x;
    const int lane = tid & 31, wid = tid >> 5;

#pragma unroll
    for (int it = 0; it < 8; it++) {
        int idx = it * 128 + tid;
        int g = idx >> 8, k = idx & 255;
        float4 v;
        v.x = X[(size_t)(row0 + 4 * g + 0) * HH + k];
        v.y = X[(size_t)(row0 + 4 * g + 1) * HH + k];
        v.z = X[(size_t)(row0 + 4 * g + 2) * HH + k];
        v.w = X[(size_t)(row0 + 4 * g + 3) * HH + k];
        *(float4*)(xs + g * (HH * 4) + k * 4) = v;
    }
    __syncthreads();

    u64 accA[8], accB[8];
#pragma unroll
    for (int p = 0; p < 8; p++) { accA[p] = 0ULL; accB[p] = 0ULL; }

    const int c = tid;
    float wA[4], wB[4];
#pragma unroll
    for (int u = 0; u < 4; u++) { wA[u] = W[u * HH + c]; wB[u] = W[u * HH + c + 128]; }

    for (int kt = 0; kt < HH; kt += 4) {
        float cAv[4], cBv[4];
#pragma unroll
        for (int u = 0; u < 4; u++) { cAv[u] = wA[u]; cBv[u] = wB[u]; }
        if (kt + 4 < HH) {
#pragma unroll
            for (int u = 0; u < 4; u++) {
                wA[u] = W[(kt + 4 + u) * HH + c];
                wB[u] = W[(kt + 4 + u) * HH + c + 128];
            }
        }
#pragma unroll
        for (int u = 0; u < 4; u++) {
            int k = kt + u;
            u64 h2a = pack2(cAv[u]);
            u64 h2b = pack2(cBv[u]);
#pragma unroll
            for (int g = 0; g < 4; g++) {
                ulonglong2 q = *(const ulonglong2*)(xs + g * (HH * 4) + k * 4);
                ffma2(accA[2 * g], q.x, h2a); ffma2(accA[2 * g + 1], q.y, h2a);
                ffma2(accB[2 * g], q.x, h2b); ffma2(accB[2 * g + 1], q.y, h2b);
            }
        }
    }

    const float a1A = a1[c], a1B = a1[c + 128];
    const float a2A = a2[c], a2B = a2[c + 128];
    float s1p[16], s2p[16];
    float* ob = hout + (size_t)row0 * HH + c;
#pragma unroll
    for (int p = 0; p < 8; p++) {
        float2 vA = unpack2(accA[p]);
        float2 vB = unpack2(accB[p]);
        ob[(size_t)(2 * p) * HH]           = vA.x;
        ob[(size_t)(2 * p + 1) * HH]       = vA.y;
        ob[(size_t)(2 * p) * HH + 128]     = vB.x;
        ob[(size_t)(2 * p + 1) * HH + 128] = vB.y;
        s1p[2 * p]     = vA.x * a1A + vB.x * a1B;
        s1p[2 * p + 1] = vA.y * a1A + vB.y * a1B;
        s2p[2 * p]     = vA.x * a2A + vB.x * a2B;
        s2p[2 * p + 1] = vA.y * a2A + vB.y * a2B;
    }
#pragma unroll
    for (int r = 0; r < 16; r++) {
#pragma unroll
        for (int o = 16; o; o >>= 1) {
            s1p[r] += __shfl_xor_sync(0xffffffffu, s1p[r], o);
            s2p[r] += __shfl_xor_sync(0xffffffffu, s2p[r], o);
        }
        if (lane == 0) { red[r * 4 + wid] = s1p[r]; red[64 + r * 4 + wid] = s2p[r]; }
    }
    __syncthreads();
    if (tid < 32) {
        int r = tid & 15;
        int base = (tid < 16) ? 0 : 64;
        float s = red[base + r * 4] + red[base + r * 4 + 1] + red[base + r * 4 + 2] + red[base + r * 4 + 3];
        if (tid < 16) s1o[row0 + r] = s; else s2o[row0 + r] = s;
    }
}

// ============================================================================
// attention: out = relu( softmax_row( mask( leaky(s1_i + s2_j) ) ) @ h )
// 16 rows/block, 256 threads. Phase B: warp = (8-row group) x (128-col half)
// x (512-j segment): wid = jseg*4 + rg*2 + half. Lane owns 4 consecutive
// cols. Per warp-j: 2 broadcast LDS.128 + 1 LDG.128 + 16 FFMA2. 2 partials
// per output reduced through the att smem buffer. ~70 regs -> 3 blocks/SM.
// ============================================================================
__global__ __launch_bounds__(256, 3) void att_kernel(
    const uint32_t* __restrict__ mask, const float* __restrict__ h,
    const float* __restrict__ s1, const float* __restrict__ s2,
    float* __restrict__ out)
{
    extern __shared__ float att[];        // 16384 floats (64KB); reused for partials
    __shared__ uint32_t msk[16 * 32];     // 2KB: 16 rows x 32 words
    __shared__ float red[128];            // 16 rows x 8 warps
    __shared__ float rinv[16];
    __shared__ float s2mx[8];
    __shared__ float s2max_sh;

    const int b = blockIdx.y;
    const int i0 = blockIdx.x * 16;
    const int tid = threadIdx.x;
    const int lane = tid & 31, wid = tid >> 5;

    // load this block's 16 mask rows (512 words, 256 threads -> uint2 each)
    {
        const uint2* mg = (const uint2*)(mask + ((size_t)b * NN + i0) * 32);
        ((uint2*)msk)[tid] = mg[tid];
    }

    const float* s2b = s2 + b * NN;
    float s2v[4];
    float m = -3.4e38f;
#pragma unroll
    for (int u = 0; u < 4; u++) { s2v[u] = s2b[u * 256 + tid]; m = fmaxf(m, s2v[u]); }
#pragma unroll
    for (int o = 16; o; o >>= 1) m = fmaxf(m, __shfl_xor_sync(0xffffffffu, m, o));
    if (lane == 0) s2mx[wid] = m;
    __syncthreads();
    if (tid == 0) {
        float mm = s2mx[0];
#pragma unroll
        for (int w = 1; w < 8; w++) mm = fmaxf(mm, s2mx[w]);
        s2max_sh = mm;
    }
    __syncthreads();
    const float s2max = s2max_sh;

    // -------- phase A: unnormalized probs into att, rowsum partials --------
#pragma unroll
    for (int g = 0; g < 4; g++) {
        float s1v[4], mi[4], sum[4];
#pragma unroll
        for (int q = 0; q < 4; q++) {
            s1v[q] = s1[b * NN + i0 + 4 * g + q];
            mi[q] = leaky(s1v[q] + s2max);
            sum[q] = 0.f;
        }
#pragma unroll
        for (int u = 0; u < 4; u++) {
            int j = u * 256 + tid;
            float s2j = s2v[u];
            float4 pv;
#pragma unroll
            for (int q = 0; q < 4; q++) {
                uint32_t mw = msk[(4 * g + q) * 32 + u * 8 + wid];  // broadcast LDS
                float e = leaky(s1v[q] + s2j);
                float p = ((mw >> lane) & 1u) ? __expf(e - mi[q]) : 0.f;
                ((float*)&pv)[q] = p;
                sum[q] += p;
            }
            *(float4*)(att + g * 4096 + j * 4) = pv;   // conflict-free STS.128
        }
#pragma unroll
        for (int q = 0; q < 4; q++) {
#pragma unroll
            for (int o = 16; o; o >>= 1) sum[q] += __shfl_xor_sync(0xffffffffu, sum[q], o);
            if (lane == 0) red[(4 * g + q) * 8 + wid] = sum[q];
        }
    }
    __syncthreads();
    if (tid < 16) {
        float s = 0.f;
#pragma unroll
        for (int w = 0; w < 8; w++) s += red[tid * 8 + w];
        rinv[tid] = 1.0f / s;
    }
    __syncthreads();

    // -------- phase B: partial C[8,128] per warp over its 512-j segment ----
    const int half = wid & 1;            // column half
    const int rg   = (wid >> 1) & 1;     // row group (8 rows)
    const int jseg = wid >> 2;           // j segment 0..1 (512 j each)
    const int j0 = jseg * 512;

    u64 acc[4][4];   // [row-pair][col]; rp -> rows rg*8+2rp, +1
#pragma unroll
    for (int rp = 0; rp < 4; rp++)
#pragma unroll
        for (int cc = 0; cc < 4; cc++) acc[rp][cc] = 0ULL;

    const float* hp = h + b * (NN * HH) + half * 128 + lane * 4;
    const float* a0p = att + (2 * rg) * 4096;       // quad 2rg   (rows 8rg..+3)
    const float* a1p = a0p + 4096;                  // quad 2rg+1 (rows 8rg+4..+7)

    float4 hbuf[4];
#pragma unroll
    for (int u = 0; u < 4; u++) hbuf[u] = *(const float4*)(hp + (j0 + u) * HH);

    for (int jt = j0; jt < j0 + 508; jt += 4) {
#pragma unroll
        for (int u = 0; u < 4; u++) {
            const int j = jt + u;
            float4 hv = hbuf[u];
            hbuf[u] = *(const float4*)(hp + (j + 4) * HH);
            ulonglong2 aq0 = *(const ulonglong2*)(a0p + j * 4);
            ulonglong2 aq1 = *(const ulonglong2*)(a1p + j * 4);
            u64 h0 = pack2(hv.x), h1 = pack2(hv.y), h2 = pack2(hv.z), h3 = pack2(hv.w);
            ffma2(acc[0][0], aq0.x, h0); ffma2(acc[0][1], aq0.x, h1);
            ffma2(acc[0][2], aq0.x, h2); ffma2(acc[0][3], aq0.x, h3);
            ffma2(acc[1][0], aq0.y, h0); ffma2(acc[1][1], aq0.y, h1);
            ffma2(acc[1][2], aq0.y, h2); ffma2(acc[1][3], aq0.y, h3);
            ffma2(acc[2][0], aq1.x, h0); ffma2(acc[2][1], aq1.x, h1);
            ffma2(acc[2][2], aq1.x, h2); ffma2(acc[2][3], aq1.x, h3);
            ffma2(acc[3][0], aq1.y, h0); ffma2(acc[3][1], aq1.y, h1);
            ffma2(acc[3][2], aq1.y, h2); ffma2(acc[3][3], aq1.y, h3);
        }
    }
    // tail: last 4 j (no prefetch)
#pragma unroll
    for (int u = 0; u < 4; u++) {
        const int j = j0 + 508 + u;
        float4 hv = hbuf[u];
        ulonglong2 aq0 = *(const ulonglong2*)(a0p + j * 4);
        ulonglong2 aq1 = *(const ulonglong2*)(a1p + j * 4);
        u64 h0 = pack2(hv.x), h1 = pack2(hv.y), h2 = pack2(hv.z), h3 = pack2(hv.w);
        ffma2(acc[0][0], aq0.x, h0); ffma2(acc[0][1], aq0.x, h1);
        ffma2(acc[0][2], aq0.x, h2); ffma2(acc[0][3], aq0.x, h3);
        ffma2(acc[1][0], aq0.y, h0); ffma2(acc[1][1], aq0.y, h1);
        ffma2(acc[1][2], aq0.y, h2); ffma2(acc[1][3], aq0.y, h3);
        ffma2(acc[2][0], aq1.x, h0); ffma2(acc[2][1], aq1.x, h1);
        ffma2(acc[2][2], aq1.x, h2); ffma2(acc[2][3], aq1.x, h3);
        ffma2(acc[3][0], aq1.y, h0); ffma2(acc[3][1], aq1.y, h1);
        ffma2(acc[3][2], aq1.y, h2); ffma2(acc[3][3], aq1.y, h3);
    }

    // -------- reduce 2 jseg partials through smem (reuse att) --------
    __syncthreads();   // all warps done reading att
    {
        // partials layout: part[jseg][row][col], row-major 16x256 per jseg
        float* part = att + jseg * 4096 + (rg * 8) * 256 + half * 128 + lane * 4;
#pragma unroll
        for (int rp = 0; rp < 4; rp++) {
            float2 c0 = unpack2(acc[rp][0]);
            float2 c1 = unpack2(acc[rp][1]);
            float2 c2 = unpack2(acc[rp][2]);
            float2 c3 = unpack2(acc[rp][3]);
            *(float4*)(part + (2 * rp) * 256)     = make_float4(c0.x, c1.x, c2.x, c3.x);
            *(float4*)(part + (2 * rp + 1) * 256) = make_float4(c0.y, c1.y, c2.y, c3.y);
        }
    }
    __syncthreads();

    // combine: thread handles row r = tid>>4, col-quads (tid&15) + {0,16,32,48}
    {
        const int r = tid >> 4;
        const int qbase = tid & 15;
        const float ri = rinv[r];
        float* ob = out + ((size_t)b * NN + i0 + r) * HH;
#pragma unroll
        for (int k = 0; k < 4; k++) {
            const int q = qbase + k * 16;          // quad 0..63, col = q*4
            float4 v0 = *(const float4*)(att + r * 256 + q * 4);
            float4 v1 = *(const float4*)(att + 4096 + r * 256 + q * 4);
            float4 o;
            o.x = fmaxf((v0.x + v1.x) * ri, 0.f);
            o.y = fmaxf((v0.y + v1.y) * ri, 0.f);
            o.z = fmaxf((v0.z + v1.z) * ri, 0.f);
            o.w = fmaxf((v0.w + v1.w) * ri, 0.f);
            *(float4*)(ob + q * 4) = o;
        }
    }
}

// ---------------- pooling partials: 8 segments of 128 rows ----------------
__global__ __launch_bounds__(256) void pool_partial_kernel(
    const float* __restrict__ x, float* __restrict__ pool)
{
    const int seg = blockIdx.x, b = blockIdx.y, c = threadIdx.x;
    const float* xb = x + ((size_t)b * NN + seg * 128) * HH + c;
    float s = 0.f, m = -3.4e38f;
#pragma unroll 8
    for (int n = 0; n < 128; n++) {
        float v = xb[(size_t)n * HH];
        s += v;
        m = fmaxf(m, v);
    }
    float* pb = pool + ((size_t)b * 8 + seg) * 2 * HH;
    pb[c] = s;
    pb[HH + c] = m;
}

// ---------------- combine + 2-layer MLP ----------------
__global__ __launch_bounds__(256) void mlp_kernel(
    const float* __restrict__ pool, const float* __restrict__ W1,
    const float* __restrict__ b1, const float* __restrict__ W2,
    const float* __restrict__ b2, float* __restrict__ gout)
{
    __shared__ float g0[HH];
    __shared__ float t1[HH];
    const int b = blockIdx.x, c = threadIdx.x;
    const float* pb = pool + (size_t)b * 8 * 2 * HH;

    float s = 0.f, m = -3.4e38f;
#pragma unroll
    for (int seg = 0; seg < 8; seg++) {
        s += pb[seg * 2 * HH + c];
        m = fmaxf(m, pb[seg * 2 * HH + HH + c]);
    }
    g0[c] = s * (1.0f / NN) + m;
    __syncthreads();

    float a = b1[c];
#pragma unroll 4
    for (int k = 0; k < HH; k++) a += g0[k] * W1[k * HH + c];
    t1[c] = fmaxf(a, 0.f);
    __syncthreads();

    float a2 = b2[c];
#pragma unroll 4
    for (int k = 0; k < HH; k++) a2 += t1[k] * W2[k * HH + c];
    gout[b * HH + c] = a2;
}

// ---------------- launch ----------------
extern "C" void kernel_launch(void* const* d_in, const int* in_sizes, int n_in,
                              void* d_out, int out_size)
{
    const float* nf   = (const float*)d_in[0];
    const float* adj  = (const float*)d_in[1];
    const float* embW = (const float*)d_in[2];
    const float* embB = (const float*)d_in[3];
    const float* W0   = (const float*)d_in[4];
    const float* a10  = (const float*)d_in[5];
    const float* a20  = (const float*)d_in[6];
    const float* W1   = (const float*)d_in[7];
    const float* a11  = (const float*)d_in[8];
    const float* a21  = (const float*)d_in[9];
    const float* gW1  = (const float*)d_in[10];
    const float* gb1  = (const float*)d_in[11];
    const float* gW2  = (const float*)d_in[12];
    const float* gb2  = (const float*)d_in[13];

    float* out  = (float*)d_out;
    float* xout = out;                              // [B,N,H]
    float* gout = out + (size_t)BB * NN * HH;       // [B,H]

    float *xb, *hb, *s1b, *s2b, *poolb;
    uint32_t* maskb;
    cudaGetSymbolAddress((void**)&xb,    g_x);
    cudaGetSymbolAddress((void**)&hb,    g_h);
    cudaGetSymbolAddress((void**)&s1b,   g_s1);
    cudaGetSymbolAddress((void**)&s2b,   g_s2);
    cudaGetSymbolAddress((void**)&maskb, g_mask);
    cudaGetSymbolAddress((void**)&poolb, g_pool);

    cudaFuncSetAttribute(att_kernel, cudaFuncAttributeMaxDynamicSharedMemorySize, 64 * 1024);

    const int mrows = BB * NN;
    dim3 blk128(128);

    pack_adj_kernel<<<BB * NN * NN / 256, 256>>>(adj, maskb);
    embed_kernel<<<mrows / 16, blk128>>>(nf, embW, embB, xb);

    // layer 0
    gemm_s1s2_kernel<<<mrows / 16, blk128>>>(xb, W0, a10, a20, hb, s1b, s2b);
    att_kernel<<<dim3(NN / 16, BB), 256, 64 * 1024>>>(maskb, hb, s1b, s2b, xb);

    // layer 1
    gemm_s1s2_kernel<<<mrows / 16, blk128>>>(xb, W1, a11, a21, hb, s1b, s2b);
    att_kernel<<<dim3(NN / 16, BB), 256, 64 * 1024>>>(maskb, hb, s1b, s2b, xout);

    // pooling + MLP head
    pool_partial_kernel<<<dim3(8, BB), 256>>>(xout, poolb);
    mlp_kernel<<<BB, 256>>>(poolb, gW1, gb1, gW2, gb2, gout);
}